// round 1
// baseline (speedup 1.0000x reference)
#include <cuda_runtime.h>
#include <cstdint>

#define Bsz 16
#define QLEN 512
#define VLEN 512
#define HID 1024
#define NH 4
#define CHN 10
#define DIM 256
#define NB (NH*Bsz)   /* 64 */

// ---------------- scratch (device globals; no allocation allowed) ----------
__device__ float g_conv[NB*CHN*VLEN];          // (64,10,512)
__device__ float g_loc [Bsz*VLEN*HID];         // (16,512,1024) merged-head layout
__device__ float g_q   [Bsz*QLEN*HID];
__device__ float g_v   [Bsz*VLEN*HID];
__device__ float g_qq  [NB*QLEN*DIM];
__device__ float g_kk  [NB*VLEN*DIM];
__device__ float g_vv  [NB*VLEN*DIM];
__device__ float g_ctx [Bsz*QLEN*HID];
__device__ float g_attn[(size_t)NB*QLEN*VLEN]; // fallback if harness only wants `out`

// ---------------- conv1d over prev_attn -----------------------------------
__global__ void conv_k(const float* __restrict__ prev,
                       const float* __restrict__ w,
                       const float* __restrict__ cb)
{
    int idx = blockIdx.x*blockDim.x + threadIdx.x;     // NB*CHN*VLEN
    if (idx >= NB*CHN*VLEN) return;
    int vl = idx % VLEN;
    int c  = (idx / VLEN) % CHN;
    int bn = idx / (VLEN*CHN);
    const float* p = prev + (size_t)bn*VLEN;
    float w0 = w[c*3+0], w1 = w[c*3+1], w2 = w[c*3+2];
    float s = cb[c] + p[vl]*w1;
    if (vl > 0)       s += p[vl-1]*w0;
    if (vl < VLEN-1)  s += p[vl+1]*w2;
    g_conv[idx] = s;
}

// ---------------- loc = einsum(conv, Wloc) into merged-head layout ---------
__global__ void loc_k(const float* __restrict__ Wloc)
{
    int idx = blockIdx.x*blockDim.x + threadIdx.x;     // (Bsz*VLEN*HID)/4
    const int D4 = DIM/4;
    if (idx >= Bsz*VLEN*HID/4) return;
    int d4 = idx % D4;
    int h  = (idx / D4) % NH;
    int vl = (idx / (D4*NH)) % VLEN;
    int b  = idx / (D4*NH*VLEN);
    int d  = d4*4;
    float a0=0.f,a1=0.f,a2=0.f,a3=0.f;
    const float* cv = g_conv + ((size_t)(b*NH+h)*CHN)*VLEN + vl;
    #pragma unroll
    for (int c = 0; c < CHN; c++) {
        float cc = cv[(size_t)c*VLEN];
        const float* wl = Wloc + c*DIM + d;
        a0 += cc*wl[0]; a1 += cc*wl[1]; a2 += cc*wl[2]; a3 += cc*wl[3];
    }
    ((float4*)g_loc)[idx] = make_float4(a0,a1,a2,a3);
}

// ---------------- one SGEMM kernel, 6 fused modes ---------------------------
// MODE 0: q   = query @ Wq + bq                       M=8192 N=1024 K=1024
// MODE 1: v   = value @ Wv + bias + loc (A2=loc)      M=8192 N=1024 K=1024
// MODE 2: qq/kk/vv = head_view(src) @ sw + sb         batched 64, M=512 N=256 K=256
// MODE 3: scores = qq @ kk^T * (1/16)                 batched 64, M=512 N=512 K=256 (B transposed)
// MODE 4: ctx = attn @ vv  -> merged-head scatter     batched 64, M=512 N=256 K=512
// MODE 5: out = tanh(ctx@Wout_top + query@Wout_bot + bout)  M=8192 N=1024 K=2048
template<int MODE>
__global__ __launch_bounds__(256) void gemm_k(
    const float* __restrict__ A, const float* __restrict__ A2,
    const float* __restrict__ Bw, const float* __restrict__ bias,
    float* __restrict__ C)
{
    constexpr int BM=128, BN=128, BK=8;
    constexpr bool TB  = (MODE==3);
    constexpr int K    = (MODE<=1)?1024 : (MODE==2)?256 : (MODE==3)?256 : (MODE==4)?512 : 2048;
    constexpr int LDA  = (MODE<=2)?1024 : (MODE==3)?256 : (MODE==4)?512 : 1024;
    constexpr int LDB  = (MODE<=1)?1024 : (MODE==2)?256 : (MODE==3)?256 : (MODE==4)?256 : 1024;
    constexpr int LDC  = (MODE<=1)?1024 : (MODE==2)?256 : (MODE==3)?512 : (MODE==4)?1024 : 1024;

    const int m0 = blockIdx.y*BM, n0 = blockIdx.x*BN;
    const int z  = blockIdx.z;

    const float* Ab = A; const float* Bb = Bw; float* Cb = C;
    if (MODE==2) {
        int b = z & 15, h = z >> 4;                 // n = h*Bsz + b
        Ab = A + (size_t)b*QLEN*HID + (size_t)h*DIM;
        Cb = C + (size_t)z*QLEN*DIM;
    } else if (MODE==3) {
        Ab = A  + (size_t)z*QLEN*DIM;
        Bb = Bw + (size_t)z*VLEN*DIM;
        Cb = C  + (size_t)z*QLEN*VLEN;
    } else if (MODE==4) {
        int b = z & 15, h = z >> 4;
        Ab = A  + (size_t)z*QLEN*VLEN;
        Bb = Bw + (size_t)z*VLEN*DIM;
        Cb = C  + (size_t)b*QLEN*HID + (size_t)h*DIM;
    }

    __shared__ float As[BK][BM+4];
    __shared__ float Bs[BK][BN+4];

    const int tid = threadIdx.x;
    const int ar_ = tid >> 1, ac_ = (tid & 1)*4;    // A (and TB-B) load mapping
    const int tr  = (tid >> 4) << 3;                // 16x16 thread grid, 8x8 microtile
    const int tc  = (tid & 15) << 3;

    float acc[8][8] = {};

    for (int k0 = 0; k0 < K; k0 += BK) {
        const float* Ap = Ab;
        int kcol = k0;
        if (MODE==5 && k0 >= 1024) { Ap = A2; kcol = k0 - 1024; }

        float4 av = *(const float4*)(Ap + (size_t)(m0+ar_)*LDA + kcol + ac_);
        As[ac_+0][ar_]=av.x; As[ac_+1][ar_]=av.y; As[ac_+2][ar_]=av.z; As[ac_+3][ar_]=av.w;

        if (!TB) {
            int br_ = tid >> 5, bc_ = (tid & 31)*4;
            float4 bv = *(const float4*)(Bb + (size_t)(k0+br_)*LDB + n0 + bc_);
            *(float4*)&Bs[br_][bc_] = bv;
        } else {
            float4 bv = *(const float4*)(Bb + (size_t)(n0+ar_)*LDB + k0 + ac_);
            Bs[ac_+0][ar_]=bv.x; Bs[ac_+1][ar_]=bv.y; Bs[ac_+2][ar_]=bv.z; Bs[ac_+3][ar_]=bv.w;
        }
        __syncthreads();

        #pragma unroll
        for (int kk = 0; kk < BK; kk++) {
            float ar[8], br[8];
            *(float4*)&ar[0] = *(const float4*)&As[kk][tr];
            *(float4*)&ar[4] = *(const float4*)&As[kk][tr+4];
            *(float4*)&br[0] = *(const float4*)&Bs[kk][tc];
            *(float4*)&br[4] = *(const float4*)&Bs[kk][tc+4];
            #pragma unroll
            for (int i = 0; i < 8; i++)
                #pragma unroll
                for (int j = 0; j < 8; j++)
                    acc[i][j] += ar[i]*br[j];
        }
        __syncthreads();
    }

    #pragma unroll
    for (int i = 0; i < 8; i++) {
        int m = m0 + tr + i;
        #pragma unroll
        for (int j4 = 0; j4 < 8; j4 += 4) {
            float4 v;
            #pragma unroll
            for (int t = 0; t < 4; t++) {
                int n = n0 + tc + j4 + t;
                float x = acc[i][j4+t];
                if      (MODE==0) x += bias[n];
                else if (MODE==1) x += bias[n] + A2[(size_t)m*HID + n];
                else if (MODE==2) x += bias[n];
                else if (MODE==3) x *= 0.0625f;     // 1/sqrt(256)
                else if (MODE==5) x = tanhf(x + bias[n]);
                (&v.x)[t] = x;
            }
            *(float4*)&Cb[(size_t)m*LDC + n0 + tc + j4] = v;
        }
    }
}

// ---------------- row softmax over attn (warp per 512-wide row) ------------
__global__ void softmax_k(float* __restrict__ attn)
{
    int gw   = (blockIdx.x*blockDim.x + threadIdx.x) >> 5;
    int lane = threadIdx.x & 31;
    if (gw >= NB*QLEN) return;
    float* row = attn + (size_t)gw*VLEN;
    float4 v[4];
    float mx = -1e30f;
    #pragma unroll
    for (int r = 0; r < 4; r++) {
        v[r] = *(float4*)(row + (size_t)(lane + r*32)*4);
        mx = fmaxf(mx, fmaxf(fmaxf(v[r].x, v[r].y), fmaxf(v[r].z, v[r].w)));
    }
    #pragma unroll
    for (int o = 16; o; o >>= 1) mx = fmaxf(mx, __shfl_xor_sync(0xffffffffu, mx, o));
    float s = 0.f;
    #pragma unroll
    for (int r = 0; r < 4; r++) {
        v[r].x = expf(v[r].x - mx); v[r].y = expf(v[r].y - mx);
        v[r].z = expf(v[r].z - mx); v[r].w = expf(v[r].w - mx);
        s += v[r].x + v[r].y + v[r].z + v[r].w;
    }
    #pragma unroll
    for (int o = 16; o; o >>= 1) s += __shfl_xor_sync(0xffffffffu, s, o);
    float inv = 1.f / s;
    #pragma unroll
    for (int r = 0; r < 4; r++) {
        v[r].x *= inv; v[r].y *= inv; v[r].z *= inv; v[r].w *= inv;
        *(float4*)(row + (size_t)(lane + r*32)*4) = v[r];
    }
}

// ---------------- host launch ----------------------------------------------
static float* symaddr_gq()   { void* p; cudaGetSymbolAddress(&p, g_q);    return (float*)p; }
static float* symaddr_gv()   { void* p; cudaGetSymbolAddress(&p, g_v);    return (float*)p; }
static float* symaddr_gqq()  { void* p; cudaGetSymbolAddress(&p, g_qq);   return (float*)p; }
static float* symaddr_gkk()  { void* p; cudaGetSymbolAddress(&p, g_kk);   return (float*)p; }
static float* symaddr_gvv()  { void* p; cudaGetSymbolAddress(&p, g_vv);   return (float*)p; }
static float* symaddr_gctx() { void* p; cudaGetSymbolAddress(&p, g_ctx);  return (float*)p; }
static float* symaddr_gloc() { void* p; cudaGetSymbolAddress(&p, g_loc);  return (float*)p; }
static float* symaddr_gattn(){ void* p; cudaGetSymbolAddress(&p, g_attn); return (float*)p; }

extern "C" void kernel_launch(void* const* d_in, const int* in_sizes, int n_in,
                              void* d_out, int out_size)
{
    const float* query  = (const float*)d_in[0];
    const float* value  = (const float*)d_in[1];
    const float* prev   = (const float*)d_in[2];
    const float* conv_w = (const float*)d_in[3];
    const float* conv_b = (const float*)d_in[4];
    const float* Wq     = (const float*)d_in[5];
    const float* bq     = (const float*)d_in[6];
    const float* Wv     = (const float*)d_in[7];
    const float* Wloc   = (const float*)d_in[8];
    const float* bias   = (const float*)d_in[9];
    const float* Wout   = (const float*)d_in[10];
    const float* bout   = (const float*)d_in[11];
    const float* swq    = (const float*)d_in[12];
    const float* sbq    = (const float*)d_in[13];
    const float* swk    = (const float*)d_in[14];
    const float* sbk    = (const float*)d_in[15];
    const float* swv    = (const float*)d_in[16];
    const float* sbv    = (const float*)d_in[17];

    float* out  = (float*)d_out;
    float* qb   = symaddr_gq();
    float* vb   = symaddr_gv();
    float* qqb  = symaddr_gqq();
    float* kkb  = symaddr_gkk();
    float* vvb  = symaddr_gvv();
    float* ctxb = symaddr_gctx();
    float* locb = symaddr_gloc();

    const long long OUT_ELEMS  = (long long)Bsz*QLEN*HID;      // 8388608
    const long long ATTN_ELEMS = (long long)NB*QLEN*VLEN;      // 16777216
    float* attn = ((long long)out_size >= OUT_ELEMS + ATTN_ELEMS)
                    ? out + OUT_ELEMS : symaddr_gattn();

    conv_k<<<(NB*CHN*VLEN + 255)/256, 256>>>(prev, conv_w, conv_b);
    loc_k <<<(Bsz*VLEN*HID/4 + 255)/256, 256>>>(Wloc);

    gemm_k<0><<<dim3(8,64,1),  256>>>(query, nullptr, Wq,   bq,   qb);
    gemm_k<1><<<dim3(8,64,1),  256>>>(value, locb,    Wv,   bias, vb);
    gemm_k<2><<<dim3(2,4,64),  256>>>(qb,    nullptr, swq,  sbq,  qqb);
    gemm_k<2><<<dim3(2,4,64),  256>>>(vb,    nullptr, swk,  sbk,  kkb);
    gemm_k<2><<<dim3(2,4,64),  256>>>(vb,    nullptr, swv,  sbv,  vvb);
    gemm_k<3><<<dim3(4,4,64),  256>>>(qqb,   nullptr, kkb,  nullptr, attn);
    softmax_k<<<(NB*QLEN*32 + 255)/256, 256>>>(attn);
    gemm_k<4><<<dim3(2,4,64),  256>>>(attn,  nullptr, vvb,  nullptr, ctxb);
    gemm_k<5><<<dim3(8,64,1),  256>>>(ctxb,  query,   Wout, bout, out);
}

// round 4
// speedup vs baseline: 2.9906x; 2.9906x over previous
#include <cuda_runtime.h>
#include <cstdint>

#define Bsz 16
#define QLEN 512
#define VLEN 512
#define HID 1024
#define NH 4
#define CHN 10
#define DIM 256
#define NB (NH*Bsz)   /* 64 */

// ---------------- scratch (device globals; no allocation allowed) ----------
__device__ float g_conv[NB*CHN*VLEN];          // (64,10,512)
__device__ float g_loc [Bsz*VLEN*HID];         // (16,512,1024) merged-head layout
__device__ float g_q   [Bsz*QLEN*HID];
__device__ float g_v   [Bsz*VLEN*HID];
__device__ float g_qq  [NB*QLEN*DIM];
__device__ float g_kk  [NB*VLEN*DIM];
__device__ float g_vv  [NB*VLEN*DIM];
__device__ float g_ctx [Bsz*QLEN*HID];
__device__ float g_attn[(size_t)NB*QLEN*VLEN]; // fallback if harness only wants `out`

// ---------------- small helpers --------------------------------------------
__device__ __forceinline__ uint32_t f2tf(float x) {
    uint32_t r;
    asm("cvt.rna.tf32.f32 %0, %1;" : "=r"(r) : "f"(x));
    return r;
}
__device__ __forceinline__ void cp16(float* dst, const float* src) {
    uint32_t d = (uint32_t)__cvta_generic_to_shared(dst);
    asm volatile("cp.async.cg.shared.global [%0], [%1], 16;" :: "r"(d), "l"(src));
}
__device__ __forceinline__ void mma8(float* c, const uint32_t* a, const uint32_t* b) {
    asm volatile(
        "mma.sync.aligned.m16n8k8.row.col.f32.tf32.tf32.f32 "
        "{%0,%1,%2,%3}, {%4,%5,%6,%7}, {%8,%9}, {%0,%1,%2,%3};"
        : "+f"(c[0]), "+f"(c[1]), "+f"(c[2]), "+f"(c[3])
        : "r"(a[0]), "r"(a[1]), "r"(a[2]), "r"(a[3]), "r"(b[0]), "r"(b[1]));
}

// ---------------- conv1d over prev_attn -----------------------------------
__global__ void conv_k(const float* __restrict__ prev,
                       const float* __restrict__ w,
                       const float* __restrict__ cb)
{
    int idx = blockIdx.x*blockDim.x + threadIdx.x;     // NB*CHN*VLEN
    if (idx >= NB*CHN*VLEN) return;
    int vl = idx % VLEN;
    int c  = (idx / VLEN) % CHN;
    int bn = idx / (VLEN*CHN);
    const float* p = prev + (size_t)bn*VLEN;
    float w0 = w[c*3+0], w1 = w[c*3+1], w2 = w[c*3+2];
    float s = cb[c] + p[vl]*w1;
    if (vl > 0)       s += p[vl-1]*w0;
    if (vl < VLEN-1)  s += p[vl+1]*w2;
    g_conv[idx] = s;
}

// ---------------- loc = einsum(conv, Wloc) into merged-head layout ---------
__global__ void loc_k(const float* __restrict__ Wloc)
{
    int idx = blockIdx.x*blockDim.x + threadIdx.x;     // (Bsz*VLEN*HID)/4
    const int D4 = DIM/4;
    if (idx >= Bsz*VLEN*HID/4) return;
    int d4 = idx % D4;
    int h  = (idx / D4) % NH;
    int vl = (idx / (D4*NH)) % VLEN;
    int b  = idx / (D4*NH*VLEN);
    int d  = d4*4;
    float a0=0.f,a1=0.f,a2=0.f,a3=0.f;
    const float* cv = g_conv + ((size_t)(b*NH+h)*CHN)*VLEN + vl;
    #pragma unroll
    for (int c = 0; c < CHN; c++) {
        float cc = cv[(size_t)c*VLEN];
        const float* wl = Wloc + c*DIM + d;
        a0 += cc*wl[0]; a1 += cc*wl[1]; a2 += cc*wl[2]; a3 += cc*wl[3];
    }
    ((float4*)g_loc)[idx] = make_float4(a0,a1,a2,a3);
}

// ---------------- TF32 tensor-core GEMM, 6 fused modes ----------------------
// MODE 0: g_q  = query @ Wq + bq                          M=8192 N=1024 K=1024
// MODE 1: g_v  = value @ Wv + bias + g_loc                M=8192 N=1024 K=1024
// MODE 2: VAR 0/1/2 -> g_qq/g_kk/g_vv = head(g_q|g_v)@sw+sb  batch 64, 512x256x256
// MODE 3: attn = g_qq @ g_kk^T * (1/16)   (VAR1: C=g_attn)   batch 64, 512x512x256
// MODE 4: g_ctx = attn @ g_vv             (VAR1: A=g_attn)   batch 64, 512x256x512
// MODE 5: out(param) = tanh([g_ctx|query] @ Wout + bout)  M=8192 N=1024 K=2048
template<int MODE, int VAR>
__global__ __launch_bounds__(256) void mma_k(
    const float* __restrict__ P0, const float* __restrict__ Bw,
    const float* __restrict__ bias, float* __restrict__ Cext)
{
    constexpr bool TB  = (MODE==3);
    constexpr int K    = (MODE<=1)?1024 : (MODE==2)?256 : (MODE==3)?256 : (MODE==4)?512 : 2048;
    constexpr int LDA  = (MODE<=2)?1024 : (MODE==3)?256 : (MODE==4)?512 : 1024;
    constexpr int LDB  = (MODE<=1)?1024 : (MODE==2)?256 : (MODE==3)?256 : (MODE==4)?256 : 1024;
    constexpr int LDC  = (MODE<=1)?1024 : (MODE==2)?256 : (MODE==3)?512 : (MODE==4)?1024 : 1024;
    constexpr int A_STAGE = 128*20;
    constexpr int B_STAGE = TB ? 128*20 : 16*136;
    constexpr int NS   = K/16;

    __shared__ float SA[2*A_STAGE];
    __shared__ float SB[2*B_STAGE];

    const int m0 = blockIdx.y*128, n0 = blockIdx.x*128;
    const int z  = blockIdx.z;

    const float* Abase =
        (MODE==0 || MODE==1) ? P0 :
        (MODE==2) ? (VAR==0 ? g_q : g_v) :
        (MODE==3) ? g_qq :
        (MODE==4) ? (VAR==1 ? g_attn : P0) : g_ctx;
    const float* Bbase =
        (MODE==3) ? g_kk : (MODE==4) ? g_vv : Bw;
    float* Cbase =
        (MODE==0) ? g_q  : (MODE==1) ? g_v :
        (MODE==2) ? (VAR==0 ? g_qq : (VAR==1 ? g_kk : g_vv)) :
        (MODE==3) ? (VAR==1 ? g_attn : Cext) :
        (MODE==4) ? g_ctx : Cext;

    const float* Ab = Abase; const float* Bb = Bbase; float* Cb = Cbase;
    if (MODE==2) {
        int b = z & 15, h = z >> 4;
        Ab = Abase + (size_t)b*QLEN*HID + (size_t)h*DIM;
        Cb = Cbase + (size_t)z*QLEN*DIM;
    } else if (MODE==3) {
        Ab = Abase + (size_t)z*QLEN*DIM;
        Bb = Bbase + (size_t)z*VLEN*DIM;
        Cb = Cbase + (size_t)z*QLEN*VLEN;
    } else if (MODE==4) {
        int b = z & 15, h = z >> 4;
        Ab = Abase + (size_t)z*QLEN*VLEN;
        Bb = Bbase + (size_t)z*VLEN*DIM;
        Cb = Cbase + (size_t)b*QLEN*HID + (size_t)h*DIM;
    }

    const int tid  = threadIdx.x;
    const int lane = tid & 31, wid = tid >> 5;
    const int wm   = wid >> 2, wn = wid & 3;        // 2x4 warp grid
    const int gid  = lane >> 2, tig = lane & 3;

    float acc[4][4][4] = {};

    auto load_stage = [&](int s, int buf) {
        int k0 = s*16;
        const float* Ap = Ab; int kc = k0;
        if (MODE==5 && k0 >= 1024) { Ap = P0; kc = k0 - 1024; }   // concat: query half
        float* sa = SA + buf*A_STAGE;
        #pragma unroll
        for (int i = 0; i < 2; i++) {
            int r = i*64 + (tid>>2), c = (tid&3)*4;
            cp16(sa + r*20 + c, Ap + (size_t)(m0+r)*LDA + kc + c);
        }
        float* sb = SB + buf*B_STAGE;
        if (!TB) {
            #pragma unroll
            for (int i = 0; i < 2; i++) {
                int r = i*8 + (tid>>5), c = (tid&31)*4;
                cp16(sb + r*136 + c, Bb + (size_t)(k0+r)*LDB + n0 + c);
            }
        } else {
            #pragma unroll
            for (int i = 0; i < 2; i++) {
                int r = i*64 + (tid>>2), c = (tid&3)*4;
                cp16(sb + r*20 + c, Bb + (size_t)(n0+r)*LDB + k0 + c);
            }
        }
        asm volatile("cp.async.commit_group;");
    };

    auto compute_stage = [&](int buf) {
        const float* sa = SA + buf*A_STAGE;
        const float* sb = SB + buf*B_STAGE;
        #pragma unroll
        for (int kk = 0; kk < 2; kk++) {
            const int kc = kk*8;
            uint32_t af[4][4];
            #pragma unroll
            for (int mt = 0; mt < 4; mt++) {
                int r = wm*64 + mt*16 + gid;
                af[mt][0] = f2tf(sa[(r  )*20 + kc + tig    ]);
                af[mt][1] = f2tf(sa[(r+8)*20 + kc + tig    ]);
                af[mt][2] = f2tf(sa[(r  )*20 + kc + tig + 4]);
                af[mt][3] = f2tf(sa[(r+8)*20 + kc + tig + 4]);
            }
            uint32_t bf[4][2];
            #pragma unroll
            for (int nt = 0; nt < 4; nt++) {
                int cb = wn*32 + nt*8 + gid;
                if (!TB) {
                    bf[nt][0] = f2tf(sb[(kc+tig  )*136 + cb]);
                    bf[nt][1] = f2tf(sb[(kc+tig+4)*136 + cb]);
                } else {
                    bf[nt][0] = f2tf(sb[cb*20 + kc + tig    ]);
                    bf[nt][1] = f2tf(sb[cb*20 + kc + tig + 4]);
                }
            }
            #pragma unroll
            for (int mt = 0; mt < 4; mt++)
                #pragma unroll
                for (int nt = 0; nt < 4; nt++)
                    mma8(acc[mt][nt], af[mt], bf[nt]);
        }
    };

    load_stage(0, 0);
    for (int s = 0; s < NS; s++) {
        if (s+1 < NS) {
            load_stage(s+1, (s+1)&1);
            asm volatile("cp.async.wait_group 1;");
        } else {
            asm volatile("cp.async.wait_group 0;");
        }
        __syncthreads();
        compute_stage(s&1);
        __syncthreads();
    }

    #pragma unroll
    for (int mt = 0; mt < 4; mt++) {
        #pragma unroll
        for (int nt = 0; nt < 4; nt++) {
            int row = m0 + wm*64 + mt*16 + gid;
            int col = n0 + wn*32 + nt*8 + 2*tig;
            float* c = acc[mt][nt];
            #pragma unroll
            for (int half = 0; half < 2; half++) {
                int r = row + half*8;
                float x0 = c[half*2+0], x1 = c[half*2+1];
                if (MODE==0 || MODE==2) {
                    x0 += bias[col]; x1 += bias[col+1];
                } else if (MODE==1) {
                    float2 l = *(const float2*)&g_loc[(size_t)r*HID + col];
                    x0 += bias[col]   + l.x;
                    x1 += bias[col+1] + l.y;
                } else if (MODE==3) {
                    x0 *= 0.0625f; x1 *= 0.0625f;   // 1/sqrt(256)
                } else if (MODE==5) {
                    x0 = tanhf(x0 + bias[col]);
                    x1 = tanhf(x1 + bias[col+1]);
                }
                float2 v; v.x = x0; v.y = x1;
                *(float2*)&Cb[(size_t)r*LDC + col] = v;
            }
        }
    }
}

// ---------------- row softmax (warp per 512-wide row); GL=1 -> g_attn ------
template<int GL>
__global__ void softmax_k(float* __restrict__ attn_ext)
{
    int gw   = (blockIdx.x*blockDim.x + threadIdx.x) >> 5;
    int lane = threadIdx.x & 31;
    if (gw >= NB*QLEN) return;
    float* base = (GL==1) ? g_attn : attn_ext;
    float* row = base + (size_t)gw*VLEN;
    float4 v[4];
    float mx = -1e30f;
    #pragma unroll
    for (int r = 0; r < 4; r++) {
        v[r] = *(float4*)(row + (size_t)(lane + r*32)*4);
        mx = fmaxf(mx, fmaxf(fmaxf(v[r].x, v[r].y), fmaxf(v[r].z, v[r].w)));
    }
    #pragma unroll
    for (int o = 16; o; o >>= 1) mx = fmaxf(mx, __shfl_xor_sync(0xffffffffu, mx, o));
    float s = 0.f;
    #pragma unroll
    for (int r = 0; r < 4; r++) {
        v[r].x = expf(v[r].x - mx); v[r].y = expf(v[r].y - mx);
        v[r].z = expf(v[r].z - mx); v[r].w = expf(v[r].w - mx);
        s += v[r].x + v[r].y + v[r].z + v[r].w;
    }
    #pragma unroll
    for (int o = 16; o; o >>= 1) s += __shfl_xor_sync(0xffffffffu, s, o);
    float inv = 1.f / s;
    #pragma unroll
    for (int r = 0; r < 4; r++) {
        v[r].x *= inv; v[r].y *= inv; v[r].z *= inv; v[r].w *= inv;
        *(float4*)(row + (size_t)(lane + r*32)*4) = v[r];
    }
}

extern "C" void kernel_launch(void* const* d_in, const int* in_sizes, int n_in,
                              void* d_out, int out_size)
{
    const float* query  = (const float*)d_in[0];
    const float* value  = (const float*)d_in[1];
    const float* prev   = (const float*)d_in[2];
    const float* conv_w = (const float*)d_in[3];
    const float* conv_b = (const float*)d_in[4];
    const float* Wq     = (const float*)d_in[5];
    const float* bq     = (const float*)d_in[6];
    const float* Wv     = (const float*)d_in[7];
    const float* Wloc   = (const float*)d_in[8];
    const float* bias   = (const float*)d_in[9];
    const float* Wout   = (const float*)d_in[10];
    const float* bout   = (const float*)d_in[11];
    const float* swq    = (const float*)d_in[12];
    const float* sbq    = (const float*)d_in[13];
    const float* swk    = (const float*)d_in[14];
    const float* sbk    = (const float*)d_in[15];
    const float* swv    = (const float*)d_in[16];
    const float* sbv    = (const float*)d_in[17];

    float* out = (float*)d_out;

    const long long OUT_ELEMS  = (long long)Bsz*QLEN*HID;      // 8388608
    const long long ATTN_ELEMS = (long long)NB*QLEN*VLEN;      // 16777216
    const bool attn_in_out = ((long long)out_size >= OUT_ELEMS + ATTN_ELEMS);

    conv_k<<<(NB*CHN*VLEN + 255)/256, 256>>>(prev, conv_w, conv_b);
    loc_k <<<(Bsz*VLEN*HID/4 + 255)/256, 256>>>(Wloc);

    mma_k<0,0><<<dim3(8,64,1), 256>>>(query,   Wq,  bq,   nullptr);
    mma_k<1,0><<<dim3(8,64,1), 256>>>(value,   Wv,  bias, nullptr);
    mma_k<2,0><<<dim3(2,4,64), 256>>>(nullptr, swq, sbq,  nullptr);
    mma_k<2,1><<<dim3(2,4,64), 256>>>(nullptr, swk, sbk,  nullptr);
    mma_k<2,2><<<dim3(2,4,64), 256>>>(nullptr, swv, sbv,  nullptr);

    if (attn_in_out) {
        float* attn = out + OUT_ELEMS;
        mma_k<3,0><<<dim3(4,4,64), 256>>>(nullptr, nullptr, nullptr, attn);
        softmax_k<0><<<(NB*QLEN*32 + 255)/256, 256>>>(attn);
        mma_k<4,0><<<dim3(2,4,64), 256>>>(attn,    nullptr, nullptr, nullptr);
    } else {
        mma_k<3,1><<<dim3(4,4,64), 256>>>(nullptr, nullptr, nullptr, nullptr);
        softmax_k<1><<<(NB*QLEN*32 + 255)/256, 256>>>(nullptr);
        mma_k<4,1><<<dim3(2,4,64), 256>>>(nullptr, nullptr, nullptr, nullptr);
    }

    mma_k<5,0><<<dim3(8,64,1), 256>>>(query,   Wout, bout, out);
}

// round 5
// speedup vs baseline: 3.0750x; 1.0282x over previous
#include <cuda_runtime.h>
#include <cstdint>

#define Bsz 16
#define QLEN 512
#define VLEN 512
#define HID 1024
#define NH 4
#define CHN 10
#define DIM 256
#define NB (NH*Bsz)   /* 64 */

// ---------------- scratch (device globals; no allocation allowed) ----------
__device__ float g_conv[NB*CHN*VLEN];
__device__ float g_loc [Bsz*VLEN*HID];
__device__ float g_q   [Bsz*QLEN*HID];          // tf32-rounded on write
__device__ float g_v   [Bsz*VLEN*HID];          // tf32-rounded on write
__device__ float g_qq  [NB*QLEN*DIM];           // tf32-rounded on write
__device__ float g_kk  [NB*VLEN*DIM];           // tf32-rounded on write
__device__ float g_vv  [NB*VLEN*DIM];           // tf32-rounded on write
__device__ float g_ctx [Bsz*QLEN*HID];          // tf32-rounded on write
__device__ float g_attn[(size_t)NB*QLEN*VLEN];  // fallback attn (exact f32)
// pre-rounded copies of external GEMM operands
__device__ float g_qr  [Bsz*QLEN*HID];
__device__ float g_vr  [Bsz*VLEN*HID];
__device__ float g_wq  [HID*HID];
__device__ float g_wv  [HID*HID];
__device__ float g_wout[2*HID*HID];
__device__ float g_swq [DIM*DIM];
__device__ float g_swk [DIM*DIM];
__device__ float g_swv [DIM*DIM];

// ---------------- helpers ---------------------------------------------------
__device__ __forceinline__ uint32_t f2tf(float x) {
    uint32_t r; asm("cvt.rna.tf32.f32 %0, %1;" : "=r"(r) : "f"(x)); return r;
}
__device__ __forceinline__ float tf32r(float x) {
    uint32_t r; asm("cvt.rna.tf32.f32 %0, %1;" : "=r"(r) : "f"(x));
    return __uint_as_float(r);
}
__device__ __forceinline__ void cp16(float* dst, const float* src) {
    uint32_t d = (uint32_t)__cvta_generic_to_shared(dst);
    asm volatile("cp.async.cg.shared.global [%0], [%1], 16;" :: "r"(d), "l"(src));
}
__device__ __forceinline__ void mma8(float* c, const uint32_t* a, const uint32_t* b) {
    asm volatile(
        "mma.sync.aligned.m16n8k8.row.col.f32.tf32.tf32.f32 "
        "{%0,%1,%2,%3}, {%4,%5,%6,%7}, {%8,%9}, {%0,%1,%2,%3};"
        : "+f"(c[0]), "+f"(c[1]), "+f"(c[2]), "+f"(c[3])
        : "r"(a[0]), "r"(a[1]), "r"(a[2]), "r"(a[3]), "r"(b[0]), "r"(b[1]));
}

// ---------------- prep: round external operands to tf32 ---------------------
// DST: 0 g_qr, 1 g_vr, 2 g_wq, 3 g_wv, 4 g_wout, 5 g_swq, 6 g_swk, 7 g_swv
template<int DST>
__global__ void round_k(const float* __restrict__ src, int n4)
{
    float* dst =
        (DST==0) ? g_qr : (DST==1) ? g_vr : (DST==2) ? g_wq :
        (DST==3) ? g_wv : (DST==4) ? g_wout :
        (DST==5) ? g_swq : (DST==6) ? g_swk : g_swv;
    int i = blockIdx.x*blockDim.x + threadIdx.x;
    if (i >= n4) return;
    float4 v = ((const float4*)src)[i];
    v.x = tf32r(v.x); v.y = tf32r(v.y); v.z = tf32r(v.z); v.w = tf32r(v.w);
    ((float4*)dst)[i] = v;
}

// ---------------- conv1d over prev_attn -------------------------------------
__global__ void conv_k(const float* __restrict__ prev,
                       const float* __restrict__ w,
                       const float* __restrict__ cb)
{
    int idx = blockIdx.x*blockDim.x + threadIdx.x;
    if (idx >= NB*CHN*VLEN) return;
    int vl = idx % VLEN;
    int c  = (idx / VLEN) % CHN;
    int bn = idx / (VLEN*CHN);
    const float* p = prev + (size_t)bn*VLEN;
    float w0 = w[c*3+0], w1 = w[c*3+1], w2 = w[c*3+2];
    float s = cb[c] + p[vl]*w1;
    if (vl > 0)       s += p[vl-1]*w0;
    if (vl < VLEN-1)  s += p[vl+1]*w2;
    g_conv[idx] = s;
}

// ---------------- loc = einsum(conv, Wloc) into merged-head layout ----------
__global__ void loc_k(const float* __restrict__ Wloc)
{
    int idx = blockIdx.x*blockDim.x + threadIdx.x;
    const int D4 = DIM/4;
    if (idx >= Bsz*VLEN*HID/4) return;
    int d4 = idx % D4;
    int h  = (idx / D4) % NH;
    int vl = (idx / (D4*NH)) % VLEN;
    int b  = idx / (D4*NH*VLEN);
    int d  = d4*4;
    float a0=0.f,a1=0.f,a2=0.f,a3=0.f;
    const float* cv = g_conv + ((size_t)(b*NH+h)*CHN)*VLEN + vl;
    #pragma unroll
    for (int c = 0; c < CHN; c++) {
        float cc = cv[(size_t)c*VLEN];
        const float* wl = Wloc + c*DIM + d;
        a0 += cc*wl[0]; a1 += cc*wl[1]; a2 += cc*wl[2]; a3 += cc*wl[3];
    }
    ((float4*)g_loc)[idx] = make_float4(a0,a1,a2,a3);
}

// ---------------- TF32 tensor-core GEMM, 6 fused modes -----------------------
// All GEMM operands are pre-rounded tf32 bits except MODE4's A (attn, exact
// f32, converted in-loop). Epilogues round results destined to feed later GEMMs.
// MODE 0: g_q  = g_qr @ g_wq + bq            (round)   M=8192 N=1024 K=1024
// MODE 1: g_v  = g_vr @ g_wv + bias + g_loc  (round)   M=8192 N=1024 K=1024
// MODE 2: VAR 0/1/2 -> g_qq/g_kk/g_vv = head(g_q|g_v)@g_sw*+sb (round) 64x 512x256x256
// MODE 3: attn = g_qq @ g_kk^T * (1/16)      (exact)   64x 512x512x256 (B^T)
// MODE 4: g_ctx = attn @ g_vv                (round)   64x 512x256x512
// MODE 5: out = tanh([g_ctx|g_qr] @ g_wout + bout)     M=8192 N=1024 K=2048
template<int MODE, int VAR>
__global__ __launch_bounds__(256) void mma_k(
    const float* __restrict__ P0, const float* __restrict__ bias,
    float* __restrict__ Cext)
{
    constexpr bool TB   = (MODE==3);
    constexpr bool CVTA = (MODE==4);   // attn A is exact f32
    constexpr int K    = (MODE<=1)?1024 : (MODE==2)?256 : (MODE==3)?256 : (MODE==4)?512 : 2048;
    constexpr int LDA  = (MODE<=2)?1024 : (MODE==3)?256 : (MODE==4)?512 : 1024;
    constexpr int LDB  = (MODE<=1)?1024 : (MODE==2)?256 : (MODE==3)?256 : (MODE==4)?256 : 1024;
    constexpr int LDC  = (MODE<=1)?1024 : (MODE==2)?256 : (MODE==3)?512 : (MODE==4)?1024 : 1024;
    constexpr int A_STAGE = 128*20;
    constexpr int B_STAGE = TB ? 128*20 : 16*136;
    constexpr int NS   = K/16;   // always even

    __shared__ float SA[2*A_STAGE];
    __shared__ float SB[2*B_STAGE];

    const int m0 = blockIdx.y*128, n0 = blockIdx.x*128;
    const int z  = blockIdx.z;

    const float* Abase =
        (MODE==0) ? g_qr : (MODE==1) ? g_vr :
        (MODE==2) ? (VAR==0 ? g_q : g_v) :
        (MODE==3) ? g_qq :
        (MODE==4) ? (VAR==1 ? g_attn : P0) : g_ctx;
    const float* Bbase =
        (MODE==0) ? g_wq : (MODE==1) ? g_wv :
        (MODE==2) ? (VAR==0 ? g_swq : (VAR==1 ? g_swk : g_swv)) :
        (MODE==3) ? g_kk : (MODE==4) ? g_vv : g_wout;
    float* Cbase =
        (MODE==0) ? g_q  : (MODE==1) ? g_v :
        (MODE==2) ? (VAR==0 ? g_qq : (VAR==1 ? g_kk : g_vv)) :
        (MODE==3) ? (VAR==1 ? g_attn : Cext) :
        (MODE==4) ? g_ctx : Cext;

    const float* Ab = Abase; const float* Bb = Bbase; float* Cb = Cbase;
    if (MODE==2) {
        int b = z & 15, h = z >> 4;
        Ab = Abase + (size_t)b*QLEN*HID + (size_t)h*DIM;
        Cb = Cbase + (size_t)z*QLEN*DIM;
    } else if (MODE==3) {
        Ab = Abase + (size_t)z*QLEN*DIM;
        Bb = Bbase + (size_t)z*VLEN*DIM;
        Cb = Cbase + (size_t)z*QLEN*VLEN;
    } else if (MODE==4) {
        int b = z & 15, h = z >> 4;
        Ab = Abase + (size_t)z*QLEN*VLEN;
        Bb = Bbase + (size_t)z*VLEN*DIM;
        Cb = Cbase + (size_t)b*QLEN*HID + (size_t)h*DIM;
    }

    const int tid  = threadIdx.x;
    const int lane = tid & 31, wid = tid >> 5;
    const int wm   = wid >> 2, wn = wid & 3;        // 2x4 warp grid
    const int gid  = lane >> 2, tig = lane & 3;

    float acc[4][4][4] = {};

    auto load_stage = [&](int s, int buf) {
        int k0 = s*16;
        const float* Ap = Ab; int kc = k0;
        if (MODE==5 && k0 >= 1024) { Ap = g_qr; kc = k0 - 1024; }   // concat half
        float* sa = SA + buf*A_STAGE;
        #pragma unroll
        for (int i = 0; i < 2; i++) {
            int r = i*64 + (tid>>2), c = (tid&3)*4;
            cp16(sa + r*20 + c, Ap + (size_t)(m0+r)*LDA + kc + c);
        }
        float* sb = SB + buf*B_STAGE;
        if (!TB) {
            #pragma unroll
            for (int i = 0; i < 2; i++) {
                int r = i*8 + (tid>>5), c = (tid&31)*4;
                cp16(sb + r*136 + c, Bb + (size_t)(k0+r)*LDB + n0 + c);
            }
        } else {
            #pragma unroll
            for (int i = 0; i < 2; i++) {
                int r = i*64 + (tid>>2), c = (tid&3)*4;
                cp16(sb + r*20 + c, Bb + (size_t)(n0+r)*LDB + k0 + c);
            }
        }
        asm volatile("cp.async.commit_group;");
    };

    auto compute_stage = [&](int buf) {
        const float* sa = SA + buf*A_STAGE;
        const float* sb = SB + buf*B_STAGE;
        #pragma unroll
        for (int kk = 0; kk < 2; kk++) {
            const int kc = kk*8;
            uint32_t af[4][4];
            #pragma unroll
            for (int mt = 0; mt < 4; mt++) {
                int r = wm*64 + mt*16 + gid;
                if (CVTA) {
                    af[mt][0] = f2tf(sa[(r  )*20 + kc + tig    ]);
                    af[mt][1] = f2tf(sa[(r+8)*20 + kc + tig    ]);
                    af[mt][2] = f2tf(sa[(r  )*20 + kc + tig + 4]);
                    af[mt][3] = f2tf(sa[(r+8)*20 + kc + tig + 4]);
                } else {
                    af[mt][0] = __float_as_uint(sa[(r  )*20 + kc + tig    ]);
                    af[mt][1] = __float_as_uint(sa[(r+8)*20 + kc + tig    ]);
                    af[mt][2] = __float_as_uint(sa[(r  )*20 + kc + tig + 4]);
                    af[mt][3] = __float_as_uint(sa[(r+8)*20 + kc + tig + 4]);
                }
            }
            uint32_t bf[4][2];
            #pragma unroll
            for (int nt = 0; nt < 4; nt++) {
                int cb = wn*32 + nt*8 + gid;
                if (!TB) {
                    bf[nt][0] = __float_as_uint(sb[(kc+tig  )*136 + cb]);
                    bf[nt][1] = __float_as_uint(sb[(kc+tig+4)*136 + cb]);
                } else {
                    bf[nt][0] = __float_as_uint(sb[cb*20 + kc + tig    ]);
                    bf[nt][1] = __float_as_uint(sb[cb*20 + kc + tig + 4]);
                }
            }
            #pragma unroll
            for (int mt = 0; mt < 4; mt++)
                #pragma unroll
                for (int nt = 0; nt < 4; nt++)
                    mma8(acc[mt][nt], af[mt], bf[nt]);
        }
    };

    // mainloop unrolled x2: stage-buffer index is compile-time constant
    load_stage(0, 0);
    for (int s = 0; s < NS; s += 2) {
        load_stage(s+1, 1);
        asm volatile("cp.async.wait_group 1;");
        __syncthreads();
        compute_stage(0);
        __syncthreads();
        if (s+2 < NS) {
            load_stage(s+2, 0);
            asm volatile("cp.async.wait_group 1;");
        } else {
            asm volatile("cp.async.wait_group 0;");
        }
        __syncthreads();
        compute_stage(1);
        __syncthreads();
    }

    // ---- epilogue ----------------------------------------------------------
    #pragma unroll
    for (int mt = 0; mt < 4; mt++) {
        #pragma unroll
        for (int nt = 0; nt < 4; nt++) {
            int row = m0 + wm*64 + mt*16 + gid;
            int col = n0 + wn*32 + nt*8 + 2*tig;
            float* c = acc[mt][nt];
            #pragma unroll
            for (int half = 0; half < 2; half++) {
                int r = row + half*8;
                float x0 = c[half*2+0], x1 = c[half*2+1];
                if (MODE==0 || MODE==2) {
                    x0 = tf32r(x0 + bias[col]);
                    x1 = tf32r(x1 + bias[col+1]);
                } else if (MODE==1) {
                    float2 l = *(const float2*)&g_loc[(size_t)r*HID + col];
                    x0 = tf32r(x0 + bias[col]   + l.x);
                    x1 = tf32r(x1 + bias[col+1] + l.y);
                } else if (MODE==3) {
                    x0 *= 0.0625f; x1 *= 0.0625f;   // 1/sqrt(256), exact f32
                } else if (MODE==4) {
                    x0 = tf32r(x0); x1 = tf32r(x1);
                } else if (MODE==5) {
                    x0 = tanhf(x0 + bias[col]);
                    x1 = tanhf(x1 + bias[col+1]);
                }
                float2 v; v.x = x0; v.y = x1;
                *(float2*)&Cb[(size_t)r*LDC + col] = v;
            }
        }
    }
}

// ---------------- row softmax (warp per 512-wide row); GL=1 -> g_attn -------
template<int GL>
__global__ void softmax_k(float* __restrict__ attn_ext)
{
    int gw   = (blockIdx.x*blockDim.x + threadIdx.x) >> 5;
    int lane = threadIdx.x & 31;
    if (gw >= NB*QLEN) return;
    float* base = (GL==1) ? g_attn : attn_ext;
    float* row = base + (size_t)gw*VLEN;
    float4 v[4];
    float mx = -1e30f;
    #pragma unroll
    for (int r = 0; r < 4; r++) {
        v[r] = *(float4*)(row + (size_t)(lane + r*32)*4);
        mx = fmaxf(mx, fmaxf(fmaxf(v[r].x, v[r].y), fmaxf(v[r].z, v[r].w)));
    }
    #pragma unroll
    for (int o = 16; o; o >>= 1) mx = fmaxf(mx, __shfl_xor_sync(0xffffffffu, mx, o));
    float s = 0.f;
    #pragma unroll
    for (int r = 0; r < 4; r++) {
        v[r].x = expf(v[r].x - mx); v[r].y = expf(v[r].y - mx);
        v[r].z = expf(v[r].z - mx); v[r].w = expf(v[r].w - mx);
        s += v[r].x + v[r].y + v[r].z + v[r].w;
    }
    #pragma unroll
    for (int o = 16; o; o >>= 1) s += __shfl_xor_sync(0xffffffffu, s, o);
    float inv = 1.f / s;
    #pragma unroll
    for (int r = 0; r < 4; r++) {
        v[r].x *= inv; v[r].y *= inv; v[r].z *= inv; v[r].w *= inv;
        *(float4*)(row + (size_t)(lane + r*32)*4) = v[r];
    }
}

extern "C" void kernel_launch(void* const* d_in, const int* in_sizes, int n_in,
                              void* d_out, int out_size)
{
    const float* query  = (const float*)d_in[0];
    const float* value  = (const float*)d_in[1];
    const float* prev   = (const float*)d_in[2];
    const float* conv_w = (const float*)d_in[3];
    const float* conv_b = (const float*)d_in[4];
    const float* Wq     = (const float*)d_in[5];
    const float* bq     = (const float*)d_in[6];
    const float* Wv     = (const float*)d_in[7];
    const float* Wloc   = (const float*)d_in[8];
    const float* bias   = (const float*)d_in[9];
    const float* Wout   = (const float*)d_in[10];
    const float* bout   = (const float*)d_in[11];
    const float* swq    = (const float*)d_in[12];
    const float* sbq    = (const float*)d_in[13];
    const float* swk    = (const float*)d_in[14];
    const float* sbk    = (const float*)d_in[15];
    const float* swv    = (const float*)d_in[16];
    const float* sbv    = (const float*)d_in[17];

    float* out = (float*)d_out;

    const long long OUT_ELEMS  = (long long)Bsz*QLEN*HID;      // 8388608
    const long long ATTN_ELEMS = (long long)NB*QLEN*VLEN;      // 16777216
    const bool attn_in_out = ((long long)out_size >= OUT_ELEMS + ATTN_ELEMS);

    // prep: tf32-round all external GEMM operands (independent, launch first)
    round_k<0><<<(Bsz*QLEN*HID/4 + 255)/256, 256>>>(query, Bsz*QLEN*HID/4);
    round_k<1><<<(Bsz*VLEN*HID/4 + 255)/256, 256>>>(value, Bsz*VLEN*HID/4);
    round_k<2><<<(HID*HID/4     + 255)/256, 256>>>(Wq,    HID*HID/4);
    round_k<3><<<(HID*HID/4     + 255)/256, 256>>>(Wv,    HID*HID/4);
    round_k<4><<<(2*HID*HID/4   + 255)/256, 256>>>(Wout,  2*HID*HID/4);
    round_k<5><<<(DIM*DIM/4     + 255)/256, 256>>>(swq,   DIM*DIM/4);
    round_k<6><<<(DIM*DIM/4     + 255)/256, 256>>>(swk,   DIM*DIM/4);
    round_k<7><<<(DIM*DIM/4     + 255)/256, 256>>>(swv,   DIM*DIM/4);

    conv_k<<<(NB*CHN*VLEN + 255)/256, 256>>>(prev, conv_w, conv_b);
    loc_k <<<(Bsz*VLEN*HID/4 + 255)/256, 256>>>(Wloc);

    mma_k<0,0><<<dim3(8,64,1), 256>>>(nullptr, bq,   nullptr);
    mma_k<1,0><<<dim3(8,64,1), 256>>>(nullptr, bias, nullptr);
    mma_k<2,0><<<dim3(2,4,64), 256>>>(nullptr, sbq,  nullptr);
    mma_k<2,1><<<dim3(2,4,64), 256>>>(nullptr, sbk,  nullptr);
    mma_k<2,2><<<dim3(2,4,64), 256>>>(nullptr, sbv,  nullptr);

    if (attn_in_out) {
        float* attn = out + OUT_ELEMS;
        mma_k<3,0><<<dim3(4,4,64), 256>>>(nullptr, nullptr, attn);
        softmax_k<0><<<(NB*QLEN*32 + 255)/256, 256>>>(attn);
        mma_k<4,0><<<dim3(2,4,64), 256>>>(attn,    nullptr, nullptr);
    } else {
        mma_k<3,1><<<dim3(4,4,64), 256>>>(nullptr, nullptr, nullptr);
        softmax_k<1><<<(NB*QLEN*32 + 255)/256, 256>>>(nullptr);
        mma_k<4,1><<<dim3(2,4,64), 256>>>(nullptr, nullptr, nullptr);
    }

    mma_k<5,0><<<dim3(8,64,1), 256>>>(nullptr, bout, out);
}

// round 6
// speedup vs baseline: 3.1523x; 1.0251x over previous
#include <cuda_runtime.h>
#include <cstdint>

#define Bsz 16
#define QLEN 512
#define VLEN 512
#define HID 1024
#define NH 4
#define CHN 10
#define DIM 256
#define NB (NH*Bsz)   /* 64 */

// ---------------- scratch (device globals; no allocation allowed) ----------
__device__ float g_conv[NB*CHN*VLEN];
__device__ float g_loc [Bsz*VLEN*HID];
__device__ float g_q   [Bsz*QLEN*HID];          // tf32-rounded on write
__device__ float g_v   [Bsz*VLEN*HID];          // tf32-rounded on write
__device__ float g_qq  [NB*QLEN*DIM];           // tf32-rounded on write
__device__ float g_kk  [NB*VLEN*DIM];           // tf32-rounded on write
__device__ float g_vv  [NB*VLEN*DIM];           // tf32-rounded on write
__device__ float g_ctx [Bsz*QLEN*HID];          // tf32-rounded on write
__device__ float g_attn[(size_t)NB*QLEN*VLEN];  // fallback attn (exact f32)
// pre-rounded weights
__device__ float g_wq  [HID*HID];
__device__ float g_wv  [HID*HID];
__device__ float g_wout[2*HID*HID];
__device__ float g_swq [DIM*DIM];
__device__ float g_swk [DIM*DIM];
__device__ float g_swv [DIM*DIM];

// ---------------- helpers ---------------------------------------------------
__device__ __forceinline__ uint32_t f2tf(float x) {
    uint32_t r; asm("cvt.rna.tf32.f32 %0, %1;" : "=r"(r) : "f"(x)); return r;
}
__device__ __forceinline__ float tf32r(float x) {
    uint32_t r; asm("cvt.rna.tf32.f32 %0, %1;" : "=r"(r) : "f"(x));
    return __uint_as_float(r);
}
__device__ __forceinline__ void cp16(float* dst, const float* src) {
    uint32_t d = (uint32_t)__cvta_generic_to_shared(dst);
    asm volatile("cp.async.cg.shared.global [%0], [%1], 16;" :: "r"(d), "l"(src));
}
__device__ __forceinline__ void mma8(float* c, const uint32_t* a, const uint32_t* b) {
    asm volatile(
        "mma.sync.aligned.m16n8k8.row.col.f32.tf32.tf32.f32 "
        "{%0,%1,%2,%3}, {%4,%5,%6,%7}, {%8,%9}, {%0,%1,%2,%3};"
        : "+f"(c[0]), "+f"(c[1]), "+f"(c[2]), "+f"(c[3])
        : "r"(a[0]), "r"(a[1]), "r"(a[2]), "r"(a[3]), "r"(b[0]), "r"(b[1]));
}

// ---------------- prep: round ALL weights to tf32, one kernel ---------------
// float4 segment layout: wq 262144 | wv 262144 | wout 524288 | swq/swk/swv 16384 each
#define N4_WQ   (HID*HID/4)
#define N4_WOUT (2*HID*HID/4)
#define N4_SW   (DIM*DIM/4)
#define N4_TOT  (2*N4_WQ + N4_WOUT + 3*N4_SW)
__global__ void round_weights_k(const float* __restrict__ Wq,
                                const float* __restrict__ Wv,
                                const float* __restrict__ Wout,
                                const float* __restrict__ swq,
                                const float* __restrict__ swk,
                                const float* __restrict__ swv)
{
    int i = blockIdx.x*blockDim.x + threadIdx.x;
    if (i >= N4_TOT) return;
    const float* src; float* dst; int off;
    if      (i <   N4_WQ)                        { src=Wq;   dst=g_wq;   off=i; }
    else if (i < 2*N4_WQ)                        { src=Wv;   dst=g_wv;   off=i-N4_WQ; }
    else if (i < 2*N4_WQ+N4_WOUT)                { src=Wout; dst=g_wout; off=i-2*N4_WQ; }
    else if (i < 2*N4_WQ+N4_WOUT+N4_SW)          { src=swq;  dst=g_swq;  off=i-2*N4_WQ-N4_WOUT; }
    else if (i < 2*N4_WQ+N4_WOUT+2*N4_SW)        { src=swk;  dst=g_swk;  off=i-2*N4_WQ-N4_WOUT-N4_SW; }
    else                                         { src=swv;  dst=g_swv;  off=i-2*N4_WQ-N4_WOUT-2*N4_SW; }
    float4 v = ((const float4*)src)[off];
    v.x = tf32r(v.x); v.y = tf32r(v.y); v.z = tf32r(v.z); v.w = tf32r(v.w);
    ((float4*)dst)[off] = v;
}

// ---------------- conv1d over prev_attn -------------------------------------
__global__ void conv_k(const float* __restrict__ prev,
                       const float* __restrict__ w,
                       const float* __restrict__ cb)
{
    int idx = blockIdx.x*blockDim.x + threadIdx.x;
    if (idx >= NB*CHN*VLEN) return;
    int vl = idx % VLEN;
    int c  = (idx / VLEN) % CHN;
    int bn = idx / (VLEN*CHN);
    const float* p = prev + (size_t)bn*VLEN;
    float w0 = w[c*3+0], w1 = w[c*3+1], w2 = w[c*3+2];
    float s = cb[c] + p[vl]*w1;
    if (vl > 0)       s += p[vl-1]*w0;
    if (vl < VLEN-1)  s += p[vl+1]*w2;
    g_conv[idx] = s;
}

// ---------------- loc = einsum(conv, Wloc) into merged-head layout ----------
__global__ void loc_k(const float* __restrict__ Wloc)
{
    int idx = blockIdx.x*blockDim.x + threadIdx.x;
    const int D4 = DIM/4;
    if (idx >= Bsz*VLEN*HID/4) return;
    int d4 = idx % D4;
    int h  = (idx / D4) % NH;
    int vl = (idx / (D4*NH)) % VLEN;
    int b  = idx / (D4*NH*VLEN);
    int d  = d4*4;
    float a0=0.f,a1=0.f,a2=0.f,a3=0.f;
    const float* cv = g_conv + ((size_t)(b*NH+h)*CHN)*VLEN + vl;
    #pragma unroll
    for (int c = 0; c < CHN; c++) {
        float cc = cv[(size_t)c*VLEN];
        const float* wl = Wloc + c*DIM + d;
        a0 += cc*wl[0]; a1 += cc*wl[1]; a2 += cc*wl[2]; a3 += cc*wl[3];
    }
    ((float4*)g_loc)[idx] = make_float4(a0,a1,a2,a3);
}

// ---------------- TF32 tensor-core GEMM, 6 fused modes -----------------------
// CTA tile 128x128x16, 4 warps (2x2), warp tile 64x64 -> 128 B smem / MMA.
// A cvt'd in-loop for modes 0/1/4/5 (raw f32 inputs); modes 2/3 read
// pre-rounded intermediates as raw bits. B always pre-rounded bits.
// MODE 0: g_q  = cvt(query) @ g_wq + bq      (round epi)  M=8192 N=1024 K=1024
// MODE 1: g_v  = cvt(value) @ g_wv +bias+loc (round epi)  M=8192 N=1024 K=1024
// MODE 2: VAR0/1/2 -> g_qq/g_kk/g_vv = head(g_q|g_v)@g_sw* + sb (round) 64x 512x256x256
// MODE 3: attn = g_qq @ g_kk^T * (1/16)      (exact f32)  64x 512x512x256 (B^T)
// MODE 4: g_ctx = cvt(attn) @ g_vv           (round epi)  64x 512x256x512
// MODE 5: out = tanh(cvt([g_ctx|query]) @ g_wout + bout)  M=8192 N=1024 K=2048
template<int MODE, int VAR>
__global__ __launch_bounds__(128) void mma_k(
    const float* __restrict__ P0, const float* __restrict__ bias,
    float* __restrict__ Cext)
{
    constexpr bool TB   = (MODE==3);
    constexpr bool CVTA = (MODE==0 || MODE==1 || MODE==4 || MODE==5);
    constexpr int K    = (MODE<=1)?1024 : (MODE==2)?256 : (MODE==3)?256 : (MODE==4)?512 : 2048;
    constexpr int LDA  = (MODE<=2)?1024 : (MODE==3)?256 : (MODE==4)?512 : 1024;
    constexpr int LDB  = (MODE<=1)?1024 : (MODE==2)?256 : (MODE==3)?256 : (MODE==4)?256 : 1024;
    constexpr int LDC  = (MODE<=1)?1024 : (MODE==2)?256 : (MODE==3)?512 : (MODE==4)?1024 : 1024;
    constexpr int A_STAGE = 128*20;
    constexpr int B_STAGE = TB ? 128*20 : 16*136;
    constexpr int NS   = K/16;   // always even

    __shared__ float SA[2*A_STAGE];
    __shared__ float SB[2*B_STAGE];

    const int m0 = blockIdx.y*128, n0 = blockIdx.x*128;
    const int z  = blockIdx.z;

    const float* Abase =
        (MODE==0 || MODE==1) ? P0 :
        (MODE==2) ? (VAR==0 ? g_q : g_v) :
        (MODE==3) ? g_qq :
        (MODE==4) ? (VAR==1 ? g_attn : P0) : g_ctx;
    const float* Bbase =
        (MODE==0) ? g_wq : (MODE==1) ? g_wv :
        (MODE==2) ? (VAR==0 ? g_swq : (VAR==1 ? g_swk : g_swv)) :
        (MODE==3) ? g_kk : (MODE==4) ? g_vv : g_wout;
    float* Cbase =
        (MODE==0) ? g_q  : (MODE==1) ? g_v :
        (MODE==2) ? (VAR==0 ? g_qq : (VAR==1 ? g_kk : g_vv)) :
        (MODE==3) ? (VAR==1 ? g_attn : Cext) :
        (MODE==4) ? g_ctx : Cext;

    const float* Ab = Abase; const float* Bb = Bbase; float* Cb = Cbase;
    if (MODE==2) {
        int b = z & 15, h = z >> 4;
        Ab = Abase + (size_t)b*QLEN*HID + (size_t)h*DIM;
        Cb = Cbase + (size_t)z*QLEN*DIM;
    } else if (MODE==3) {
        Ab = Abase + (size_t)z*QLEN*DIM;
        Bb = Bbase + (size_t)z*VLEN*DIM;
        Cb = Cbase + (size_t)z*QLEN*VLEN;
    } else if (MODE==4) {
        int b = z & 15, h = z >> 4;
        Ab = Abase + (size_t)z*QLEN*VLEN;
        Bb = Bbase + (size_t)z*VLEN*DIM;
        Cb = Cbase + (size_t)b*QLEN*HID + (size_t)h*DIM;
    }

    const int tid  = threadIdx.x;
    const int lane = tid & 31, wid = tid >> 5;
    const int wm   = wid >> 1, wn = wid & 1;        // 2x2 warp grid
    const int gid  = lane >> 2, tig = lane & 3;

    float acc[4][8][4] = {};                         // 64x64 warp tile

    auto load_stage = [&](int s, int buf) {
        int k0 = s*16;
        const float* Ap = Ab; int kc = k0;
        if (MODE==5 && k0 >= 1024) { Ap = P0; kc = k0 - 1024; }   // concat: query half
        float* sa = SA + buf*A_STAGE;
        #pragma unroll
        for (int i = 0; i < 4; i++) {
            int r = i*32 + (tid>>2), c = (tid&3)*4;
            cp16(sa + r*20 + c, Ap + (size_t)(m0+r)*LDA + kc + c);
        }
        float* sb = SB + buf*B_STAGE;
        if (!TB) {
            #pragma unroll
            for (int i = 0; i < 4; i++) {
                int r = i*4 + (tid>>5), c = (tid&31)*4;
                cp16(sb + r*136 + c, Bb + (size_t)(k0+r)*LDB + n0 + c);
            }
        } else {
            #pragma unroll
            for (int i = 0; i < 4; i++) {
                int r = i*32 + (tid>>2), c = (tid&3)*4;
                cp16(sb + r*20 + c, Bb + (size_t)(n0+r)*LDB + k0 + c);
            }
        }
        asm volatile("cp.async.commit_group;");
    };

    auto compute_stage = [&](int buf) {
        const float* sa = SA + buf*A_STAGE;
        const float* sb = SB + buf*B_STAGE;
        #pragma unroll
        for (int kk = 0; kk < 2; kk++) {
            const int kc = kk*8;
            uint32_t af[4][4];
            #pragma unroll
            for (int mt = 0; mt < 4; mt++) {
                int r = wm*64 + mt*16 + gid;
                if (CVTA) {
                    af[mt][0] = f2tf(sa[(r  )*20 + kc + tig    ]);
                    af[mt][1] = f2tf(sa[(r+8)*20 + kc + tig    ]);
                    af[mt][2] = f2tf(sa[(r  )*20 + kc + tig + 4]);
                    af[mt][3] = f2tf(sa[(r+8)*20 + kc + tig + 4]);
                } else {
                    af[mt][0] = __float_as_uint(sa[(r  )*20 + kc + tig    ]);
                    af[mt][1] = __float_as_uint(sa[(r+8)*20 + kc + tig    ]);
                    af[mt][2] = __float_as_uint(sa[(r  )*20 + kc + tig + 4]);
                    af[mt][3] = __float_as_uint(sa[(r+8)*20 + kc + tig + 4]);
                }
            }
            uint32_t bf[8][2];
            #pragma unroll
            for (int nt = 0; nt < 8; nt++) {
                int cb = wn*64 + nt*8 + gid;
                if (!TB) {
                    bf[nt][0] = __float_as_uint(sb[(kc+tig  )*136 + cb]);
                    bf[nt][1] = __float_as_uint(sb[(kc+tig+4)*136 + cb]);
                } else {
                    bf[nt][0] = __float_as_uint(sb[cb*20 + kc + tig    ]);
                    bf[nt][1] = __float_as_uint(sb[cb*20 + kc + tig + 4]);
                }
            }
            #pragma unroll
            for (int mt = 0; mt < 4; mt++)
                #pragma unroll
                for (int nt = 0; nt < 8; nt++)
                    mma8(acc[mt][nt], af[mt], bf[nt]);
        }
    };

    // mainloop unrolled x2: stage-buffer index is compile-time constant
    load_stage(0, 0);
    for (int s = 0; s < NS; s += 2) {
        load_stage(s+1, 1);
        asm volatile("cp.async.wait_group 1;");
        __syncthreads();
        compute_stage(0);
        __syncthreads();
        if (s+2 < NS) {
            load_stage(s+2, 0);
            asm volatile("cp.async.wait_group 1;");
        } else {
            asm volatile("cp.async.wait_group 0;");
        }
        __syncthreads();
        compute_stage(1);
        __syncthreads();
    }

    // ---- epilogue ----------------------------------------------------------
    #pragma unroll
    for (int mt = 0; mt < 4; mt++) {
        #pragma unroll
        for (int nt = 0; nt < 8; nt++) {
            int row = m0 + wm*64 + mt*16 + gid;
            int col = n0 + wn*64 + nt*8 + 2*tig;
            float* c = acc[mt][nt];
            #pragma unroll
            for (int half = 0; half < 2; half++) {
                int r = row + half*8;
                float x0 = c[half*2+0], x1 = c[half*2+1];
                if (MODE==0 || MODE==2) {
                    x0 = tf32r(x0 + bias[col]);
                    x1 = tf32r(x1 + bias[col+1]);
                } else if (MODE==1) {
                    float2 l = *(const float2*)&g_loc[(size_t)r*HID + col];
                    x0 = tf32r(x0 + bias[col]   + l.x);
                    x1 = tf32r(x1 + bias[col+1] + l.y);
                } else if (MODE==3) {
                    x0 *= 0.0625f; x1 *= 0.0625f;   // 1/sqrt(256), exact f32
                } else if (MODE==4) {
                    x0 = tf32r(x0); x1 = tf32r(x1);
                } else if (MODE==5) {
                    x0 = tanhf(x0 + bias[col]);
                    x1 = tanhf(x1 + bias[col+1]);
                }
                float2 v; v.x = x0; v.y = x1;
                *(float2*)&Cb[(size_t)r*LDC + col] = v;
            }
        }
    }
}

// ---------------- row softmax (warp per 512-wide row); GL=1 -> g_attn -------
template<int GL>
__global__ void softmax_k(float* __restrict__ attn_ext)
{
    int gw   = (blockIdx.x*blockDim.x + threadIdx.x) >> 5;
    int lane = threadIdx.x & 31;
    if (gw >= NB*QLEN) return;
    float* base = (GL==1) ? g_attn : attn_ext;
    float* row = base + (size_t)gw*VLEN;
    float4 v[4];
    float mx = -1e30f;
    #pragma unroll
    for (int r = 0; r < 4; r++) {
        v[r] = *(float4*)(row + (size_t)(lane + r*32)*4);
        mx = fmaxf(mx, fmaxf(fmaxf(v[r].x, v[r].y), fmaxf(v[r].z, v[r].w)));
    }
    #pragma unroll
    for (int o = 16; o; o >>= 1) mx = fmaxf(mx, __shfl_xor_sync(0xffffffffu, mx, o));
    float s = 0.f;
    #pragma unroll
    for (int r = 0; r < 4; r++) {
        v[r].x = expf(v[r].x - mx); v[r].y = expf(v[r].y - mx);
        v[r].z = expf(v[r].z - mx); v[r].w = expf(v[r].w - mx);
        s += v[r].x + v[r].y + v[r].z + v[r].w;
    }
    #pragma unroll
    for (int o = 16; o; o >>= 1) s += __shfl_xor_sync(0xffffffffu, s, o);
    float inv = 1.f / s;
    #pragma unroll
    for (int r = 0; r < 4; r++) {
        v[r].x *= inv; v[r].y *= inv; v[r].z *= inv; v[r].w *= inv;
        *(float4*)(row + (size_t)(lane + r*32)*4) = v[r];
    }
}

extern "C" void kernel_launch(void* const* d_in, const int* in_sizes, int n_in,
                              void* d_out, int out_size)
{
    const float* query  = (const float*)d_in[0];
    const float* value  = (const float*)d_in[1];
    const float* prev   = (const float*)d_in[2];
    const float* conv_w = (const float*)d_in[3];
    const float* conv_b = (const float*)d_in[4];
    const float* Wq     = (const float*)d_in[5];
    const float* bq     = (const float*)d_in[6];
    const float* Wv     = (const float*)d_in[7];
    const float* Wloc   = (const float*)d_in[8];
    const float* bias   = (const float*)d_in[9];
    const float* Wout   = (const float*)d_in[10];
    const float* bout   = (const float*)d_in[11];
    const float* swq    = (const float*)d_in[12];
    const float* sbq    = (const float*)d_in[13];
    const float* swk    = (const float*)d_in[14];
    const float* sbk    = (const float*)d_in[15];
    const float* swv    = (const float*)d_in[16];
    const float* sbv    = (const float*)d_in[17];

    float* out = (float*)d_out;

    const long long OUT_ELEMS  = (long long)Bsz*QLEN*HID;      // 8388608
    const long long ATTN_ELEMS = (long long)NB*QLEN*VLEN;      // 16777216
    const bool attn_in_out = ((long long)out_size >= OUT_ELEMS + ATTN_ELEMS);

    round_weights_k<<<(N4_TOT + 255)/256, 256>>>(Wq, Wv, Wout, swq, swk, swv);
    conv_k<<<(NB*CHN*VLEN + 255)/256, 256>>>(prev, conv_w, conv_b);
    loc_k <<<(Bsz*VLEN*HID/4 + 255)/256, 256>>>(Wloc);

    mma_k<0,0><<<dim3(8,64,1), 128>>>(query,   bq,   nullptr);
    mma_k<1,0><<<dim3(8,64,1), 128>>>(value,   bias, nullptr);
    mma_k<2,0><<<dim3(2,4,64), 128>>>(nullptr, sbq,  nullptr);
    mma_k<2,1><<<dim3(2,4,64), 128>>>(nullptr, sbk,  nullptr);
    mma_k<2,2><<<dim3(2,4,64), 128>>>(nullptr, sbv,  nullptr);

    if (attn_in_out) {
        float* attn = out + OUT_ELEMS;
        mma_k<3,0><<<dim3(4,4,64), 128>>>(nullptr, nullptr, attn);
        softmax_k<0><<<(NB*QLEN*32 + 255)/256, 256>>>(attn);
        mma_k<4,0><<<dim3(2,4,64), 128>>>(attn,    nullptr, nullptr);
    } else {
        mma_k<3,1><<<dim3(4,4,64), 128>>>(nullptr, nullptr, nullptr);
        softmax_k<1><<<(NB*QLEN*32 + 255)/256, 256>>>(nullptr);
        mma_k<4,1><<<dim3(2,4,64), 128>>>(nullptr, nullptr, nullptr);
    }

    mma_k<5,0><<<dim3(8,64,1), 128>>>(query,   bout, out);
}

// round 9
// speedup vs baseline: 3.5517x; 1.1267x over previous
#include <cuda_runtime.h>
#include <cstdint>

#define Bsz 16
#define QLEN 512
#define VLEN 512
#define HID 1024
#define NH 4
#define CHN 10
#define DIM 256
#define NB (NH*Bsz)   /* 64 */

// ---------------- scratch (device globals; no allocation allowed) ----------
__device__ float g_conv[NB*CHN*VLEN];
__device__ float g_loc [Bsz*VLEN*HID];
__device__ float g_v   [Bsz*VLEN*HID];          // tf32-rounded on write
__device__ float g_qq  [NB*QLEN*DIM];           // tf32-rounded on write
__device__ float g_kk  [NB*VLEN*DIM];           // tf32-rounded on write
__device__ float g_vv  [NB*VLEN*DIM];           // tf32-rounded on write
__device__ float g_ctx [Bsz*QLEN*HID];          // tf32-rounded on write
__device__ float g_attn[(size_t)NB*QLEN*VLEN];  // fallback attn (exact f32)
// pre-rounded weights / folded weights
__device__ float g_wv  [HID*HID];
__device__ float g_wout[2*HID*HID];
__device__ float g_swq [DIM*DIM];
__device__ float g_swk [DIM*DIM];
__device__ float g_swv [DIM*DIM];
__device__ float g_wq2 [HID*HID];               // per-head Wq@swq (rounded)
__device__ float g_bq2 [HID];                   // bq@swq + sbq

// ---------------- helpers ---------------------------------------------------
__device__ __forceinline__ uint32_t f2tf(float x) {
    uint32_t r; asm("cvt.rna.tf32.f32 %0, %1;" : "=r"(r) : "f"(x)); return r;
}
__device__ __forceinline__ float tf32r(float x) {
    uint32_t r; asm("cvt.rna.tf32.f32 %0, %1;" : "=r"(r) : "f"(x));
    return __uint_as_float(r);
}
__device__ __forceinline__ void cp16(float* dst, const float* src) {
    uint32_t d = (uint32_t)__cvta_generic_to_shared(dst);
    asm volatile("cp.async.cg.shared.global [%0], [%1], 16;" :: "r"(d), "l"(src));
}
__device__ __forceinline__ void mma8(float* c, const uint32_t* a, const uint32_t* b) {
    asm volatile(
        "mma.sync.aligned.m16n8k8.row.col.f32.tf32.tf32.f32 "
        "{%0,%1,%2,%3}, {%4,%5,%6,%7}, {%8,%9}, {%0,%1,%2,%3};"
        : "+f"(c[0]), "+f"(c[1]), "+f"(c[2]), "+f"(c[3])
        : "r"(a[0]), "r"(a[1]), "r"(a[2]), "r"(a[3]), "r"(b[0]), "r"(b[1]));
}

// ---------------- prep: round weights to tf32, one kernel -------------------
#define N4_WV   (HID*HID/4)
#define N4_WOUT (2*HID*HID/4)
#define N4_SW   (DIM*DIM/4)
#define N4_TOT  (N4_WV + N4_WOUT + 3*N4_SW)
__global__ void round_weights_k(const float* __restrict__ Wv,
                                const float* __restrict__ Wout,
                                const float* __restrict__ swq,
                                const float* __restrict__ swk,
                                const float* __restrict__ swv)
{
    int i = blockIdx.x*blockDim.x + threadIdx.x;
    if (i >= N4_TOT) return;
    const float* src; float* dst; int off;
    if      (i < N4_WV)                    { src=Wv;   dst=g_wv;   off=i; }
    else if (i < N4_WV+N4_WOUT)            { src=Wout; dst=g_wout; off=i-N4_WV; }
    else if (i < N4_WV+N4_WOUT+N4_SW)      { src=swq;  dst=g_swq;  off=i-N4_WV-N4_WOUT; }
    else if (i < N4_WV+N4_WOUT+2*N4_SW)    { src=swk;  dst=g_swk;  off=i-N4_WV-N4_WOUT-N4_SW; }
    else                                   { src=swv;  dst=g_swv;  off=i-N4_WV-N4_WOUT-2*N4_SW; }
    float4 v = ((const float4*)src)[off];
    v.x = tf32r(v.x); v.y = tf32r(v.y); v.z = tf32r(v.z); v.w = tf32r(v.w);
    ((float4*)dst)[off] = v;
}

// ---------------- folded q bias: b2 = bq@swq + sbq (exact fp32) -------------
__global__ void b2_k(const float* __restrict__ bq, const float* __restrict__ swq,
                     const float* __restrict__ sbq)
{
    int n = blockIdx.x*blockDim.x + threadIdx.x;   // 0..1023
    if (n >= HID) return;
    int h = n >> 8, nn = n & 255;
    float s = sbq[nn];
    const float* bh = bq + h*DIM;
    for (int k = 0; k < DIM; k++) s += bh[k]*swq[k*DIM + nn];
    g_bq2[n] = s;
}

// ---------------- conv1d over prev_attn -------------------------------------
__global__ void conv_k(const float* __restrict__ prev,
                       const float* __restrict__ w,
                       const float* __restrict__ cb)
{
    int idx = blockIdx.x*blockDim.x + threadIdx.x;
    if (idx >= NB*CHN*VLEN) return;
    int vl = idx % VLEN;
    int c  = (idx / VLEN) % CHN;
    int bn = idx / (VLEN*CHN);
    const float* p = prev + (size_t)bn*VLEN;
    float w0 = w[c*3+0], w1 = w[c*3+1], w2 = w[c*3+2];
    float s = cb[c] + p[vl]*w1;
    if (vl > 0)       s += p[vl-1]*w0;
    if (vl < VLEN-1)  s += p[vl+1]*w2;
    g_conv[idx] = s;
}

// ---------------- loc = einsum(conv, Wloc) into merged-head layout ----------
__global__ void loc_k(const float* __restrict__ Wloc)
{
    int idx = blockIdx.x*blockDim.x + threadIdx.x;
    const int D4 = DIM/4;
    if (idx >= Bsz*VLEN*HID/4) return;
    int d4 = idx % D4;
    int h  = (idx / D4) % NH;
    int vl = (idx / (D4*NH)) % VLEN;
    int b  = idx / (D4*NH*VLEN);
    int d  = d4*4;
    float a0=0.f,a1=0.f,a2=0.f,a3=0.f;
    const float* cv = g_conv + ((size_t)(b*NH+h)*CHN)*VLEN + vl;
    #pragma unroll
    for (int c = 0; c < CHN; c++) {
        float cc = cv[(size_t)c*VLEN];
        const float* wl = Wloc + c*DIM + d;
        a0 += cc*wl[0]; a1 += cc*wl[1]; a2 += cc*wl[2]; a3 += cc*wl[3];
    }
    ((float4*)g_loc)[idx] = make_float4(a0,a1,a2,a3);
}

// ---------------- TF32 tensor-core GEMM --------------------------------------
// CTA tile 64x128x16, static smem double-buffer, 4 warps (2x2), warp 32x64.
// __launch_bounds__(128,3) -> 3 CTAs/SM (12 warps) for latency hiding.
// MODE 1: g_v  = cvt(value) @ g_wv + bias + loc (round)     M=8192 N=1024 K=1024
// MODE 2: z<64: g_kk = head(g_v)@g_swk + sbk; z>=64: g_vv = head(g_v)@g_swv + sbv
// MODE 3: attn = g_qq @ g_kk^T * (1/16)  (exact; VAR1 C=g_attn)  64x 512x512x256
// MODE 4: g_ctx = cvt(attn) @ g_vv       (round; VAR1 A=g_attn)  64x 512x256x512
// MODE 5: out = tanh(cvt([g_ctx|query]) @ g_wout + bout)    M=8192 N=1024 K=2048
// MODE 6: g_wq2 col-block h = cvt(Wq[:,h]) @ g_swq (round)  4x  1024x256x256
// MODE 7: g_qq = cvt(query) @ g_wq2 + g_bq2 (head scatter, round) M=8192 N=1024 K=1024
template<int MODE, int VAR>
__global__ __launch_bounds__(128, 3) void mma_k(
    const float* __restrict__ P0, const float* __restrict__ bias,
    float* __restrict__ Cext)
{
    constexpr bool TB   = (MODE==3);
    constexpr bool CVTA = (MODE==1 || MODE==4 || MODE==5 || MODE==6 || MODE==7);
    constexpr int K    = (MODE==1)?1024 : (MODE==2)?256 : (MODE==3)?256 :
                         (MODE==4)?512  : (MODE==5)?2048 : (MODE==6)?256 : 1024;
    constexpr int LDA  = (MODE==1)?1024 : (MODE==2)?1024 : (MODE==3)?256 :
                         (MODE==4)?512  : (MODE==5)?1024 : (MODE==6)?1024 : 1024;
    constexpr int LDB  = (MODE==1)?1024 : (MODE==2)?256 : (MODE==3)?256 :
                         (MODE==4)?256  : (MODE==5)?1024 : (MODE==6)?256 : 1024;
    constexpr int LDC  = (MODE==1)?1024 : (MODE==2)?256 : (MODE==3)?512 :
                         (MODE==4)?1024 : (MODE==5)?1024 : (MODE==6)?1024 : 1024;
    constexpr int A_STAGE = 64*20;
    constexpr int B_STAGE = TB ? 128*20 : 16*136;
    constexpr int NS   = K/16;   // even for all modes

    __shared__ float SA[2*A_STAGE];
    __shared__ float SB[2*B_STAGE];

    const int m0 = blockIdx.y*64, n0 = blockIdx.x*128;
    const int zz = blockIdx.z;

    const float* Ab; const float* Bb; float* Cb;
    const float* bias2 = bias;
    if (MODE==1) {
        Ab = P0; Bb = g_wv; Cb = g_v;
    } else if (MODE==2) {
        int half = zz >> 6, z = zz & 63;
        int b = z & 15, h = z >> 4;
        Ab = g_v + (size_t)b*QLEN*HID + (size_t)h*DIM;
        Bb = half ? g_swv : g_swk;
        Cb = (half ? g_vv : g_kk) + (size_t)z*QLEN*DIM;
        bias2 = half ? P0 : bias;     // P0 carries sbv, bias carries sbk
    } else if (MODE==3) {
        Ab = g_qq + (size_t)zz*QLEN*DIM;
        Bb = g_kk + (size_t)zz*VLEN*DIM;
        Cb = ((VAR==1) ? g_attn : Cext) + (size_t)zz*QLEN*VLEN;
    } else if (MODE==4) {
        int b = zz & 15, h = zz >> 4;
        Ab = ((VAR==1) ? g_attn : P0) + (size_t)zz*QLEN*VLEN;
        Bb = g_vv + (size_t)zz*VLEN*DIM;
        Cb = g_ctx + (size_t)b*QLEN*HID + (size_t)h*DIM;
    } else if (MODE==5) {
        Ab = g_ctx; Bb = g_wout; Cb = Cext;
    } else if (MODE==6) {
        Ab = P0 + (size_t)zz*DIM;     // Wq col block h
        Bb = g_swq;
        Cb = g_wq2 + (size_t)zz*DIM;
    } else { // MODE 7
        Ab = P0; Bb = g_wq2; Cb = g_qq;  // Cb unused (scatter epilogue)
    }

    const int tid  = threadIdx.x;
    const int lane = tid & 31, wid = tid >> 5;
    const int wm   = wid >> 1, wn = wid & 1;        // 2x2 warp grid
    const int gid  = lane >> 2, tig = lane & 3;

    float acc[2][8][4] = {};                         // 32x64 warp tile

    auto load_stage = [&](int s, int buf) {
        int k0 = s*16;
        const float* Ap = Ab; int kc = k0;
        if (MODE==5 && k0 >= 1024) { Ap = P0; kc = k0 - 1024; }   // concat: query half
        float* sa = SA + buf*A_STAGE;
        #pragma unroll
        for (int i = 0; i < 2; i++) {
            int r = i*32 + (tid>>2), c = (tid&3)*4;
            cp16(sa + r*20 + c, Ap + (size_t)(m0+r)*LDA + kc + c);
        }
        float* sb = SB + buf*B_STAGE;
        if (!TB) {
            #pragma unroll
            for (int i = 0; i < 4; i++) {
                int r = i*4 + (tid>>5), c = (tid&31)*4;
                cp16(sb + r*136 + c, Bb + (size_t)(k0+r)*LDB + n0 + c);
            }
        } else {
            #pragma unroll
            for (int i = 0; i < 4; i++) {
                int r = i*32 + (tid>>2), c = (tid&3)*4;
                cp16(sb + r*20 + c, Bb + (size_t)(n0+r)*LDB + k0 + c);
            }
        }
        asm volatile("cp.async.commit_group;");
    };

    auto compute_stage = [&](int buf) {
        const float* sa = SA + buf*A_STAGE;
        const float* sb = SB + buf*B_STAGE;
        #pragma unroll
        for (int kk = 0; kk < 2; kk++) {
            const int kc = kk*8;
            uint32_t af[2][4];
            #pragma unroll
            for (int mt = 0; mt < 2; mt++) {
                int r = wm*32 + mt*16 + gid;
                if (CVTA) {
                    af[mt][0] = f2tf(sa[(r  )*20 + kc + tig    ]);
                    af[mt][1] = f2tf(sa[(r+8)*20 + kc + tig    ]);
                    af[mt][2] = f2tf(sa[(r  )*20 + kc + tig + 4]);
                    af[mt][3] = f2tf(sa[(r+8)*20 + kc + tig + 4]);
                } else {
                    af[mt][0] = __float_as_uint(sa[(r  )*20 + kc + tig    ]);
                    af[mt][1] = __float_as_uint(sa[(r+8)*20 + kc + tig    ]);
                    af[mt][2] = __float_as_uint(sa[(r  )*20 + kc + tig + 4]);
                    af[mt][3] = __float_as_uint(sa[(r+8)*20 + kc + tig + 4]);
                }
            }
            uint32_t bf[8][2];
            #pragma unroll
            for (int nt = 0; nt < 8; nt++) {
                int cb = wn*64 + nt*8 + gid;
                if (!TB) {
                    bf[nt][0] = __float_as_uint(sb[(kc+tig  )*136 + cb]);
                    bf[nt][1] = __float_as_uint(sb[(kc+tig+4)*136 + cb]);
                } else {
                    bf[nt][0] = __float_as_uint(sb[cb*20 + kc + tig    ]);
                    bf[nt][1] = __float_as_uint(sb[cb*20 + kc + tig + 4]);
                }
            }
            #pragma unroll
            for (int mt = 0; mt < 2; mt++)
                #pragma unroll
                for (int nt = 0; nt < 8; nt++)
                    mma8(acc[mt][nt], af[mt], bf[nt]);
        }
    };

    load_stage(0, 0);
    for (int s = 0; s < NS; s += 2) {
        load_stage(s+1, 1);
        asm volatile("cp.async.wait_group 1;");
        __syncthreads();
        compute_stage(0);
        __syncthreads();
        if (s+2 < NS) {
            load_stage(s+2, 0);
            asm volatile("cp.async.wait_group 1;");
        } else {
            asm volatile("cp.async.wait_group 0;");
        }
        __syncthreads();
        compute_stage(1);
        __syncthreads();
    }

    // ---- epilogue ----------------------------------------------------------
    #pragma unroll
    for (int mt = 0; mt < 2; mt++) {
        #pragma unroll
        for (int nt = 0; nt < 8; nt++) {
            int row = m0 + wm*32 + mt*16 + gid;
            int col = n0 + wn*64 + nt*8 + 2*tig;
            float* c = acc[mt][nt];
            #pragma unroll
            for (int half = 0; half < 2; half++) {
                int r = row + half*8;
                float x0 = c[half*2+0], x1 = c[half*2+1];
                if (MODE==1) {
                    float2 l = *(const float2*)&g_loc[(size_t)r*HID + col];
                    x0 = tf32r(x0 + bias2[col]   + l.x);
                    x1 = tf32r(x1 + bias2[col+1] + l.y);
                } else if (MODE==2) {
                    x0 = tf32r(x0 + bias2[col]);
                    x1 = tf32r(x1 + bias2[col+1]);
                } else if (MODE==3) {
                    x0 *= 0.0625f; x1 *= 0.0625f;   // 1/sqrt(256), exact f32
                } else if (MODE==4 || MODE==6) {
                    x0 = tf32r(x0); x1 = tf32r(x1);
                } else if (MODE==5) {
                    x0 = tanhf(x0 + bias2[col]);
                    x1 = tanhf(x1 + bias2[col+1]);
                } else if (MODE==7) {
                    x0 = tf32r(x0 + g_bq2[col]);
                    x1 = tf32r(x1 + g_bq2[col+1]);
                }
                float2 v; v.x = x0; v.y = x1;
                if (MODE==7) {
                    int h = col >> 8;
                    int z = h*16 + (r >> 9);
                    *(float2*)&g_qq[(size_t)z*QLEN*DIM + (size_t)(r & 511)*DIM + (col & 255)] = v;
                } else {
                    *(float2*)&Cb[(size_t)r*LDC + col] = v;
                }
            }
        }
    }
}

// ---------------- row softmax (warp per 512-wide row); GL=1 -> g_attn -------
template<int GL>
__global__ void softmax_k(float* __restrict__ attn_ext)
{
    int gw   = (blockIdx.x*blockDim.x + threadIdx.x) >> 5;
    int lane = threadIdx.x & 31;
    if (gw >= NB*QLEN) return;
    float* base = (GL==1) ? g_attn : attn_ext;
    float* row = base + (size_t)gw*VLEN;
    float4 v[4];
    float mx = -1e30f;
    #pragma unroll
    for (int r = 0; r < 4; r++) {
        v[r] = *(float4*)(row + (size_t)(lane + r*32)*4);
        mx = fmaxf(mx, fmaxf(fmaxf(v[r].x, v[r].y), fmaxf(v[r].z, v[r].w)));
    }
    #pragma unroll
    for (int o = 16; o; o >>= 1) mx = fmaxf(mx, __shfl_xor_sync(0xffffffffu, mx, o));
    float s = 0.f;
    #pragma unroll
    for (int r = 0; r < 4; r++) {
        v[r].x = expf(v[r].x - mx); v[r].y = expf(v[r].y - mx);
        v[r].z = expf(v[r].z - mx); v[r].w = expf(v[r].w - mx);
        s += v[r].x + v[r].y + v[r].z + v[r].w;
    }
    #pragma unroll
    for (int o = 16; o; o >>= 1) s += __shfl_xor_sync(0xffffffffu, s, o);
    float inv = 1.f / s;
    #pragma unroll
    for (int r = 0; r < 4; r++) {
        v[r].x *= inv; v[r].y *= inv; v[r].z *= inv; v[r].w *= inv;
        *(float4*)(row + (size_t)(lane + r*32)*4) = v[r];
    }
}

extern "C" void kernel_launch(void* const* d_in, const int* in_sizes, int n_in,
                              void* d_out, int out_size)
{
    const float* query  = (const float*)d_in[0];
    const float* value  = (const float*)d_in[1];
    const float* prev   = (const float*)d_in[2];
    const float* conv_w = (const float*)d_in[3];
    const float* conv_b = (const float*)d_in[4];
    const float* Wq     = (const float*)d_in[5];
    const float* bq     = (const float*)d_in[6];
    const float* Wv     = (const float*)d_in[7];
    const float* Wloc   = (const float*)d_in[8];
    const float* bias   = (const float*)d_in[9];
    const float* Wout   = (const float*)d_in[10];
    const float* bout   = (const float*)d_in[11];
    const float* swq    = (const float*)d_in[12];
    const float* sbq    = (const float*)d_in[13];
    const float* swk    = (const float*)d_in[14];
    const float* sbk    = (const float*)d_in[15];
    const float* swv    = (const float*)d_in[16];
    const float* sbv    = (const float*)d_in[17];

    float* out = (float*)d_out;

    const long long OUT_ELEMS  = (long long)Bsz*QLEN*HID;      // 8388608
    const long long ATTN_ELEMS = (long long)NB*QLEN*VLEN;      // 16777216
    const bool attn_in_out = ((long long)out_size >= OUT_ELEMS + ATTN_ELEMS);

    round_weights_k<<<(N4_TOT + 255)/256, 256>>>(Wv, Wout, swq, swk, swv);
    conv_k<<<(NB*CHN*VLEN + 255)/256, 256>>>(prev, conv_w, conv_b);
    loc_k <<<(Bsz*VLEN*HID/4 + 255)/256, 256>>>(Wloc);
    b2_k  <<<(HID + 255)/256, 256>>>(bq, swq, sbq);

    // folded q path: Wq2 prep then direct qq GEMM
    mma_k<6,0><<<dim3(2,16,4),  128>>>(Wq,    nullptr, nullptr);
    mma_k<7,0><<<dim3(8,128,1), 128>>>(query, nullptr, nullptr);

    // v path
    mma_k<1,0><<<dim3(8,128,1), 128>>>(value, bias, nullptr);
    // kk (z<64) + vv (z>=64) merged; bias=sbk, P0=sbv
    mma_k<2,0><<<dim3(2,8,128), 128>>>(sbv, sbk, nullptr);

    if (attn_in_out) {
        float* attn = out + OUT_ELEMS;
        mma_k<3,0><<<dim3(4,8,64), 128>>>(nullptr, nullptr, attn);
        softmax_k<0><<<(NB*QLEN*32 + 255)/256, 256>>>(attn);
        mma_k<4,0><<<dim3(2,8,64), 128>>>(attn, nullptr, nullptr);
    } else {
        mma_k<3,1><<<dim3(4,8,64), 128>>>(nullptr, nullptr, nullptr);
        softmax_k<1><<<(NB*QLEN*32 + 255)/256, 256>>>(nullptr);
        mma_k<4,1><<<dim3(2,8,64), 128>>>(nullptr, nullptr, nullptr);
    }

    mma_k<5,0><<<dim3(8,128,1), 128>>>(query, bout, out);
}

// round 11
// speedup vs baseline: 3.7409x; 1.0532x over previous
#include <cuda_runtime.h>
#include <cstdint>

#define Bsz 16
#define QLEN 512
#define VLEN 512
#define HID 1024
#define NH 4
#define CHN 10
#define DIM 256
#define NB (NH*Bsz)   /* 64 */

// ---------------- scratch (device globals; no allocation allowed) ----------
__device__ float g_conv[NB*CHN*VLEN];
__device__ float g_v   [Bsz*VLEN*HID];          // tf32-rounded on write
__device__ float g_qq  [NB*QLEN*DIM];           // tf32-rounded on write
__device__ float g_kk  [NB*VLEN*DIM];           // tf32-rounded on write
__device__ float g_vv  [NB*VLEN*DIM];           // tf32-rounded on write
__device__ float g_ctx [Bsz*QLEN*HID];          // tf32-rounded on write
__device__ float g_attn[(size_t)NB*QLEN*VLEN];  // fallback attn (exact f32)
// pre-rounded weights / folded weights
__device__ float g_wv  [HID*HID];
__device__ float g_wout[2*HID*HID];
__device__ float g_swq [DIM*DIM];
__device__ float g_swk [DIM*DIM];
__device__ float g_swv [DIM*DIM];
__device__ float g_wq2 [HID*HID];               // per-head Wq@swq (rounded)
__device__ float g_bq2 [HID];                   // bq@swq + sbq

// ---------------- helpers ---------------------------------------------------
__device__ __forceinline__ uint32_t f2tf(float x) {
    uint32_t r; asm("cvt.rna.tf32.f32 %0, %1;" : "=r"(r) : "f"(x)); return r;
}
__device__ __forceinline__ float tf32r(float x) {
    uint32_t r; asm("cvt.rna.tf32.f32 %0, %1;" : "=r"(r) : "f"(x));
    return __uint_as_float(r);
}
__device__ __forceinline__ void cp16(float* dst, const float* src) {
    uint32_t d = (uint32_t)__cvta_generic_to_shared(dst);
    asm volatile("cp.async.cg.shared.global [%0], [%1], 16;" :: "r"(d), "l"(src));
}
__device__ __forceinline__ void mma8(float* c, const uint32_t* a, const uint32_t* b) {
    asm volatile(
        "mma.sync.aligned.m16n8k8.row.col.f32.tf32.tf32.f32 "
        "{%0,%1,%2,%3}, {%4,%5,%6,%7}, {%8,%9}, {%0,%1,%2,%3};"
        : "+f"(c[0]), "+f"(c[1]), "+f"(c[2]), "+f"(c[3])
        : "r"(a[0]), "r"(a[1]), "r"(a[2]), "r"(a[3]), "r"(b[0]), "r"(b[1]));
}

// ---------------- prep: round weights to tf32, one kernel -------------------
#define N4_WV   (HID*HID/4)
#define N4_WOUT (2*HID*HID/4)
#define N4_SW   (DIM*DIM/4)
#define N4_TOT  (N4_WV + N4_WOUT + 3*N4_SW)
__global__ void round_weights_k(const float* __restrict__ Wv,
                                const float* __restrict__ Wout,
                                const float* __restrict__ swq,
                                const float* __restrict__ swk,
                                const float* __restrict__ swv)
{
    int i = blockIdx.x*blockDim.x + threadIdx.x;
    if (i >= N4_TOT) return;
    const float* src; float* dst; int off;
    if      (i < N4_WV)                    { src=Wv;   dst=g_wv;   off=i; }
    else if (i < N4_WV+N4_WOUT)            { src=Wout; dst=g_wout; off=i-N4_WV; }
    else if (i < N4_WV+N4_WOUT+N4_SW)      { src=swq;  dst=g_swq;  off=i-N4_WV-N4_WOUT; }
    else if (i < N4_WV+N4_WOUT+2*N4_SW)    { src=swk;  dst=g_swk;  off=i-N4_WV-N4_WOUT-N4_SW; }
    else                                   { src=swv;  dst=g_swv;  off=i-N4_WV-N4_WOUT-2*N4_SW; }
    float4 v = ((const float4*)src)[off];
    v.x = tf32r(v.x); v.y = tf32r(v.y); v.z = tf32r(v.z); v.w = tf32r(v.w);
    ((float4*)dst)[off] = v;
}

// ---------------- folded q bias: b2 = bq@swq + sbq --------------------------
// 16 blocks x 64 threads, 4 split accumulators to pipeline the loads.
__global__ void b2_k(const float* __restrict__ bq, const float* __restrict__ swq,
                     const float* __restrict__ sbq)
{
    int n = blockIdx.x*64 + threadIdx.x;   // 0..1023
    if (n >= HID) return;
    int h = n >> 8, nn = n & 255;
    const float* bh = bq + h*DIM;
    float s0=0.f, s1=0.f, s2=0.f, s3=0.f;
    #pragma unroll 4
    for (int k = 0; k < DIM; k += 4) {
        s0 += bh[k+0]*swq[(k+0)*DIM + nn];
        s1 += bh[k+1]*swq[(k+1)*DIM + nn];
        s2 += bh[k+2]*swq[(k+2)*DIM + nn];
        s3 += bh[k+3]*swq[(k+3)*DIM + nn];
    }
    g_bq2[n] = sbq[nn] + ((s0+s1)+(s2+s3));
}

// ---------------- conv1d over prev_attn -------------------------------------
__global__ void conv_k(const float* __restrict__ prev,
                       const float* __restrict__ w,
                       const float* __restrict__ cb)
{
    int idx = blockIdx.x*blockDim.x + threadIdx.x;
    if (idx >= NB*CHN*VLEN) return;
    int vl = idx % VLEN;
    int c  = (idx / VLEN) % CHN;
    int bn = idx / (VLEN*CHN);
    const float* p = prev + (size_t)bn*VLEN;
    float w0 = w[c*3+0], w1 = w[c*3+1], w2 = w[c*3+2];
    float s = cb[c] + p[vl]*w1;
    if (vl > 0)       s += p[vl-1]*w0;
    if (vl < VLEN-1)  s += p[vl+1]*w2;
    g_conv[idx] = s;
}

// ---------------- TF32 tensor-core GEMM --------------------------------------
// CTA tile 64x128x16, static smem double-buffer, 4 warps (2x2), warp 32x64.
// __launch_bounds__(128,3) -> 3 CTAs/SM (12 warps).
// MODE 1: g_v = cvt(value)@g_wv + bias + loc(conv,Wloc) (round; Cext=Wloc)
//         loc computed IN EPILOGUE from g_conv x Wloc smem tiles (replaces loc_k).
// MODE 2: z<64: g_kk = head(g_v)@g_swk + sbk; z>=64: g_vv = head(g_v)@g_swv + sbv
// MODE 3: attn = g_qq @ g_kk^T * (1/16)  (exact; VAR1 C=g_attn)  64x 512x512x256
// MODE 4: g_ctx = cvt(attn) @ g_vv       (round; VAR1 A=g_attn)  64x 512x256x512
// MODE 5: out = tanh(cvt([g_ctx|query]) @ g_wout + bout)    M=8192 N=1024 K=2048
// MODE 6: g_wq2 col-block h = cvt(Wq[:,h]) @ g_swq (round)  4x  1024x256x256
// MODE 7: g_qq = cvt(query) @ g_wq2 + g_bq2 (head scatter, round) M=8192 N=1024 K=1024
template<int MODE, int VAR>
__global__ __launch_bounds__(128, 3) void mma_k(
    const float* __restrict__ P0, const float* __restrict__ bias,
    float* __restrict__ Cext)
{
    constexpr bool TB   = (MODE==3);
    constexpr bool CVTA = (MODE==1 || MODE==4 || MODE==5 || MODE==6 || MODE==7);
    constexpr int K    = (MODE==1)?1024 : (MODE==2)?256 : (MODE==3)?256 :
                         (MODE==4)?512  : (MODE==5)?2048 : (MODE==6)?256 : 1024;
    constexpr int LDA  = (MODE==1)?1024 : (MODE==2)?1024 : (MODE==3)?256 :
                         (MODE==4)?512  : (MODE==5)?1024 : (MODE==6)?1024 : 1024;
    constexpr int LDB  = (MODE==1)?1024 : (MODE==2)?256 : (MODE==3)?256 :
                         (MODE==4)?256  : (MODE==5)?1024 : (MODE==6)?256 : 1024;
    constexpr int LDC  = (MODE==1)?1024 : (MODE==2)?256 : (MODE==3)?512 :
                         (MODE==4)?1024 : (MODE==5)?1024 : (MODE==6)?1024 : 1024;
    constexpr int A_STAGE = 64*20;
    constexpr int B_STAGE = TB ? 128*20 : 16*136;
    constexpr int NS   = K/16;   // even for all modes

    __shared__ float SA[2*A_STAGE];
    __shared__ float SB[2*B_STAGE];

    const int m0 = blockIdx.y*64, n0 = blockIdx.x*128;
    const int zz = blockIdx.z;

    const float* Ab; const float* Bb; float* Cb;
    const float* bias2 = bias;
    if (MODE==1) {
        Ab = P0; Bb = g_wv; Cb = g_v;
    } else if (MODE==2) {
        int half = zz >> 6, z = zz & 63;
        int b = z & 15, h = z >> 4;
        Ab = g_v + (size_t)b*QLEN*HID + (size_t)h*DIM;
        Bb = half ? g_swv : g_swk;
        Cb = (half ? g_vv : g_kk) + (size_t)z*QLEN*DIM;
        bias2 = half ? P0 : bias;     // P0 carries sbv, bias carries sbk
    } else if (MODE==3) {
        Ab = g_qq + (size_t)zz*QLEN*DIM;
        Bb = g_kk + (size_t)zz*VLEN*DIM;
        Cb = ((VAR==1) ? g_attn : Cext) + (size_t)zz*QLEN*VLEN;
    } else if (MODE==4) {
        int b = zz & 15, h = zz >> 4;
        Ab = ((VAR==1) ? g_attn : P0) + (size_t)zz*QLEN*VLEN;
        Bb = g_vv + (size_t)zz*VLEN*DIM;
        Cb = g_ctx + (size_t)b*QLEN*HID + (size_t)h*DIM;
    } else if (MODE==5) {
        Ab = g_ctx; Bb = g_wout; Cb = Cext;
    } else if (MODE==6) {
        Ab = P0 + (size_t)zz*DIM;     // Wq col block h
        Bb = g_swq;
        Cb = g_wq2 + (size_t)zz*DIM;
    } else { // MODE 7
        Ab = P0; Bb = g_wq2; Cb = g_qq;  // Cb unused (scatter epilogue)
    }

    const int tid  = threadIdx.x;
    const int lane = tid & 31, wid = tid >> 5;
    const int wm   = wid >> 1, wn = wid & 1;        // 2x2 warp grid
    const int gid  = lane >> 2, tig = lane & 3;

    float acc[2][8][4] = {};                         // 32x64 warp tile

    auto load_stage = [&](int s, int buf) {
        int k0 = s*16;
        const float* Ap = Ab; int kc = k0;
        if (MODE==5 && k0 >= 1024) { Ap = P0; kc = k0 - 1024; }   // concat: query half
        float* sa = SA + buf*A_STAGE;
        #pragma unroll
        for (int i = 0; i < 2; i++) {
            int r = i*32 + (tid>>2), c = (tid&3)*4;
            cp16(sa + r*20 + c, Ap + (size_t)(m0+r)*LDA + kc + c);
        }
        float* sb = SB + buf*B_STAGE;
        if (!TB) {
            #pragma unroll
            for (int i = 0; i < 4; i++) {
                int r = i*4 + (tid>>5), c = (tid&31)*4;
                cp16(sb + r*136 + c, Bb + (size_t)(k0+r)*LDB + n0 + c);
            }
        } else {
            #pragma unroll
            for (int i = 0; i < 4; i++) {
                int r = i*32 + (tid>>2), c = (tid&3)*4;
                cp16(sb + r*20 + c, Bb + (size_t)(n0+r)*LDB + k0 + c);
            }
        }
        asm volatile("cp.async.commit_group;");
    };

    auto compute_stage = [&](int buf) {
        const float* sa = SA + buf*A_STAGE;
        const float* sb = SB + buf*B_STAGE;
        #pragma unroll
        for (int kk = 0; kk < 2; kk++) {
            const int kc = kk*8;
            uint32_t af[2][4];
            #pragma unroll
            for (int mt = 0; mt < 2; mt++) {
                int r = wm*32 + mt*16 + gid;
                if (CVTA) {
                    af[mt][0] = f2tf(sa[(r  )*20 + kc + tig    ]);
                    af[mt][1] = f2tf(sa[(r+8)*20 + kc + tig    ]);
                    af[mt][2] = f2tf(sa[(r  )*20 + kc + tig + 4]);
                    af[mt][3] = f2tf(sa[(r+8)*20 + kc + tig + 4]);
                } else {
                    af[mt][0] = __float_as_uint(sa[(r  )*20 + kc + tig    ]);
                    af[mt][1] = __float_as_uint(sa[(r+8)*20 + kc + tig    ]);
                    af[mt][2] = __float_as_uint(sa[(r  )*20 + kc + tig + 4]);
                    af[mt][3] = __float_as_uint(sa[(r+8)*20 + kc + tig + 4]);
                }
            }
            uint32_t bf[8][2];
            #pragma unroll
            for (int nt = 0; nt < 8; nt++) {
                int cb = wn*64 + nt*8 + gid;
                if (!TB) {
                    bf[nt][0] = __float_as_uint(sb[(kc+tig  )*136 + cb]);
                    bf[nt][1] = __float_as_uint(sb[(kc+tig+4)*136 + cb]);
                } else {
                    bf[nt][0] = __float_as_uint(sb[cb*20 + kc + tig    ]);
                    bf[nt][1] = __float_as_uint(sb[cb*20 + kc + tig + 4]);
                }
            }
            #pragma unroll
            for (int mt = 0; mt < 2; mt++)
                #pragma unroll
                for (int nt = 0; nt < 8; nt++)
                    mma8(acc[mt][nt], af[mt], bf[nt]);
        }
    };

    load_stage(0, 0);
    for (int s = 0; s < NS; s += 2) {
        load_stage(s+1, 1);
        asm volatile("cp.async.wait_group 1;");
        __syncthreads();
        compute_stage(0);
        __syncthreads();
        if (s+2 < NS) {
            load_stage(s+2, 0);
            asm volatile("cp.async.wait_group 1;");
        } else {
            asm volatile("cp.async.wait_group 0;");
        }
        __syncthreads();
        compute_stage(1);
        __syncthreads();
    }

    // ---- MODE1: stage conv/Wloc tiles for fused loc (reuse SA, now dead) ---
    float* CV = SA;            // [10][64]  conv slice (c, vl-m0)
    float* WL = SA + 640;      // [10][128] Wloc slice (c, d-base)
    if (MODE==1) {
        const int b = m0 >> 9, h = n0 >> 8, dbase = n0 & 255;
        const float* convb = g_conv + ((size_t)(b*NH+h)*CHN)*VLEN + (m0 & 511);
        const float* Wloc  = Cext;   // Cext carries Wloc for MODE1
        for (int i = tid; i < 640; i += 128) {
            int c = i >> 6, rr = i & 63;
            CV[i] = convb[(size_t)c*VLEN + rr];
        }
        for (int i = tid; i < 1280; i += 128) {
            int c = i >> 7, dd = i & 127;
            WL[i] = Wloc[c*DIM + dbase + dd];
        }
        __syncthreads();
    }

    // ---- epilogue ----------------------------------------------------------
    #pragma unroll
    for (int mt = 0; mt < 2; mt++) {
        #pragma unroll
        for (int nt = 0; nt < 8; nt++) {
            int row = m0 + wm*32 + mt*16 + gid;
            int col = n0 + wn*64 + nt*8 + 2*tig;
            float* c = acc[mt][nt];
            #pragma unroll
            for (int half = 0; half < 2; half++) {
                int r = row + half*8;
                float x0 = c[half*2+0], x1 = c[half*2+1];
                if (MODE==1) {
                    int rr = r - m0, cc = col - n0;
                    float l0 = 0.f, l1 = 0.f;
                    #pragma unroll
                    for (int ch = 0; ch < CHN; ch++) {
                        float cv = CV[ch*64 + rr];
                        l0 += cv*WL[ch*128 + cc];
                        l1 += cv*WL[ch*128 + cc + 1];
                    }
                    x0 = tf32r(x0 + bias2[col]   + l0);
                    x1 = tf32r(x1 + bias2[col+1] + l1);
                } else if (MODE==2) {
                    x0 = tf32r(x0 + bias2[col]);
                    x1 = tf32r(x1 + bias2[col+1]);
                } else if (MODE==3) {
                    x0 *= 0.0625f; x1 *= 0.0625f;   // 1/sqrt(256), exact f32
                } else if (MODE==4 || MODE==6) {
                    x0 = tf32r(x0); x1 = tf32r(x1);
                } else if (MODE==5) {
                    x0 = tanhf(x0 + bias2[col]);
                    x1 = tanhf(x1 + bias2[col+1]);
                } else if (MODE==7) {
                    x0 = tf32r(x0 + g_bq2[col]);
                    x1 = tf32r(x1 + g_bq2[col+1]);
                }
                float2 v; v.x = x0; v.y = x1;
                if (MODE==7) {
                    int h = col >> 8;
                    int z = h*16 + (r >> 9);
                    *(float2*)&g_qq[(size_t)z*QLEN*DIM + (size_t)(r & 511)*DIM + (col & 255)] = v;
                } else {
                    *(float2*)&Cb[(size_t)r*LDC + col] = v;
                }
            }
        }
    }
}

// ---------------- row softmax (warp per 512-wide row); GL=1 -> g_attn -------
template<int GL>
__global__ void softmax_k(float* __restrict__ attn_ext)
{
    int gw   = (blockIdx.x*blockDim.x + threadIdx.x) >> 5;
    int lane = threadIdx.x & 31;
    if (gw >= NB*QLEN) return;
    float* base = (GL==1) ? g_attn : attn_ext;
    float* row = base + (size_t)gw*VLEN;
    float4 v[4];
    float mx = -1e30f;
    #pragma unroll
    for (int r = 0; r < 4; r++) {
        v[r] = *(float4*)(row + (size_t)(lane + r*32)*4);
        mx = fmaxf(mx, fmaxf(fmaxf(v[r].x, v[r].y), fmaxf(v[r].z, v[r].w)));
    }
    #pragma unroll
    for (int o = 16; o; o >>= 1) mx = fmaxf(mx, __shfl_xor_sync(0xffffffffu, mx, o));
    float s = 0.f;
    #pragma unroll
    for (int r = 0; r < 4; r++) {
        v[r].x = expf(v[r].x - mx); v[r].y = expf(v[r].y - mx);
        v[r].z = expf(v[r].z - mx); v[r].w = expf(v[r].w - mx);
        s += v[r].x + v[r].y + v[r].z + v[r].w;
    }
    #pragma unroll
    for (int o = 16; o; o >>= 1) s += __shfl_xor_sync(0xffffffffu, s, o);
    float inv = 1.f / s;
    #pragma unroll
    for (int r = 0; r < 4; r++) {
        v[r].x *= inv; v[r].y *= inv; v[r].z *= inv; v[r].w *= inv;
        *(float4*)(row + (size_t)(lane + r*32)*4) = v[r];
    }
}

extern "C" void kernel_launch(void* const* d_in, const int* in_sizes, int n_in,
                              void* d_out, int out_size)
{
    const float* query  = (const float*)d_in[0];
    const float* value  = (const float*)d_in[1];
    const float* prev   = (const float*)d_in[2];
    const float* conv_w = (const float*)d_in[3];
    const float* conv_b = (const float*)d_in[4];
    const float* Wq     = (const float*)d_in[5];
    const float* bq     = (const float*)d_in[6];
    const float* Wv     = (const float*)d_in[7];
    const float* Wloc   = (const float*)d_in[8];
    const float* bias   = (const float*)d_in[9];
    const float* Wout   = (const float*)d_in[10];
    const float* bout   = (const float*)d_in[11];
    const float* swq    = (const float*)d_in[12];
    const float* sbq    = (const float*)d_in[13];
    const float* swk    = (const float*)d_in[14];
    const float* sbk    = (const float*)d_in[15];
    const float* swv    = (const float*)d_in[16];
    const float* sbv    = (const float*)d_in[17];

    float* out = (float*)d_out;

    const long long OUT_ELEMS  = (long long)Bsz*QLEN*HID;      // 8388608
    const long long ATTN_ELEMS = (long long)NB*QLEN*VLEN;      // 16777216
    const bool attn_in_out = ((long long)out_size >= OUT_ELEMS + ATTN_ELEMS);

    round_weights_k<<<(N4_TOT + 255)/256, 256>>>(Wv, Wout, swq, swk, swv);
    conv_k<<<(NB*CHN*VLEN + 255)/256, 256>>>(prev, conv_w, conv_b);
    b2_k  <<<16, 64>>>(bq, swq, sbq);

    // folded q path: Wq2 prep then direct qq GEMM
    mma_k<6,0><<<dim3(2,16,4),  128>>>(Wq,    nullptr, nullptr);
    mma_k<7,0><<<dim3(8,128,1), 128>>>(query, nullptr, nullptr);

    // v path (loc fused into epilogue; Cext carries Wloc)
    mma_k<1,0><<<dim3(8,128,1), 128>>>(value, bias, (float*)Wloc);
    // kk (z<64) + vv (z>=64) merged; bias=sbk, P0=sbv
    mma_k<2,0><<<dim3(2,8,128), 128>>>(sbv, sbk, nullptr);

    if (attn_in_out) {
        float* attn = out + OUT_ELEMS;
        mma_k<3,0><<<dim3(4,8,64), 128>>>(nullptr, nullptr, attn);
        softmax_k<0><<<(NB*QLEN*32 + 255)/256, 256>>>(attn);
        mma_k<4,0><<<dim3(2,8,64), 128>>>(attn, nullptr, nullptr);
    } else {
        mma_k<3,1><<<dim3(4,8,64), 128>>>(nullptr, nullptr, nullptr);
        softmax_k<1><<<(NB*QLEN*32 + 255)/256, 256>>>(nullptr);
        mma_k<4,1><<<dim3(2,8,64), 128>>>(nullptr, nullptr, nullptr);
    }

    mma_k<5,0><<<dim3(8,128,1), 128>>>(query, bout, out);
}

// round 12
// speedup vs baseline: 3.8472x; 1.0284x over previous
#include <cuda_runtime.h>
#include <cstdint>

#define Bsz 16
#define QLEN 512
#define VLEN 512
#define HID 1024
#define NH 4
#define CHN 10
#define DIM 256
#define NB (NH*Bsz)   /* 64 */

// ---------------- scratch (device globals; no allocation allowed) ----------
__device__ float g_conv[NB*CHN*VLEN];
__device__ float g_v   [Bsz*VLEN*HID];          // tf32-rounded on write
__device__ float g_qq  [NB*QLEN*DIM];           // tf32-rounded on write
__device__ float g_kk  [NB*VLEN*DIM];           // tf32-rounded on write
__device__ float g_vv  [NB*VLEN*DIM];           // tf32-rounded on write
__device__ float g_ctx [Bsz*QLEN*HID];          // tf32-rounded on write
__device__ float g_attn[(size_t)NB*QLEN*VLEN];  // fallback attn (exact f32)
// pre-rounded weights / folded weights
__device__ float g_wv  [HID*HID];
__device__ float g_wout[2*HID*HID];
__device__ float g_swq [DIM*DIM];
__device__ float g_swk [DIM*DIM];
__device__ float g_swv [DIM*DIM];
__device__ float g_wq2 [HID*HID];               // per-head Wq@swq (rounded)
__device__ float g_bq2 [HID];                   // bq@swq + sbq

// ---------------- helpers ---------------------------------------------------
__device__ __forceinline__ uint32_t f2tf(float x) {
    uint32_t r; asm("cvt.rna.tf32.f32 %0, %1;" : "=r"(r) : "f"(x)); return r;
}
__device__ __forceinline__ float tf32r(float x) {
    uint32_t r; asm("cvt.rna.tf32.f32 %0, %1;" : "=r"(r) : "f"(x));
    return __uint_as_float(r);
}
__device__ __forceinline__ void cp16(float* dst, const float* src) {
    uint32_t d = (uint32_t)__cvta_generic_to_shared(dst);
    asm volatile("cp.async.cg.shared.global [%0], [%1], 16;" :: "r"(d), "l"(src));
}
__device__ __forceinline__ void mma8(float* c, const uint32_t* a, const uint32_t* b) {
    asm volatile(
        "mma.sync.aligned.m16n8k8.row.col.f32.tf32.tf32.f32 "
        "{%0,%1,%2,%3}, {%4,%5,%6,%7}, {%8,%9}, {%0,%1,%2,%3};"
        : "+f"(c[0]), "+f"(c[1]), "+f"(c[2]), "+f"(c[3])
        : "r"(a[0]), "r"(a[1]), "r"(a[2]), "r"(a[3]), "r"(b[0]), "r"(b[1]));
}

// ---------------- prep: round weights to tf32, one kernel -------------------
#define N4_WV   (HID*HID/4)
#define N4_WOUT (2*HID*HID/4)
#define N4_SW   (DIM*DIM/4)
#define N4_TOT  (N4_WV + N4_WOUT + 3*N4_SW)
__global__ void round_weights_k(const float* __restrict__ Wv,
                                const float* __restrict__ Wout,
                                const float* __restrict__ swq,
                                const float* __restrict__ swk,
                                const float* __restrict__ swv)
{
    int i = blockIdx.x*blockDim.x + threadIdx.x;
    if (i >= N4_TOT) return;
    const float* src; float* dst; int off;
    if      (i < N4_WV)                    { src=Wv;   dst=g_wv;   off=i; }
    else if (i < N4_WV+N4_WOUT)            { src=Wout; dst=g_wout; off=i-N4_WV; }
    else if (i < N4_WV+N4_WOUT+N4_SW)      { src=swq;  dst=g_swq;  off=i-N4_WV-N4_WOUT; }
    else if (i < N4_WV+N4_WOUT+2*N4_SW)    { src=swk;  dst=g_swk;  off=i-N4_WV-N4_WOUT-N4_SW; }
    else                                   { src=swv;  dst=g_swv;  off=i-N4_WV-N4_WOUT-2*N4_SW; }
    float4 v = ((const float4*)src)[off];
    v.x = tf32r(v.x); v.y = tf32r(v.y); v.z = tf32r(v.z); v.w = tf32r(v.w);
    ((float4*)dst)[off] = v;
}

// ---------------- folded q bias: b2 = bq@swq + sbq --------------------------
__global__ void b2_k(const float* __restrict__ bq, const float* __restrict__ swq,
                     const float* __restrict__ sbq)
{
    int n = blockIdx.x*64 + threadIdx.x;   // 0..1023
    if (n >= HID) return;
    int h = n >> 8, nn = n & 255;
    const float* bh = bq + h*DIM;
    float s0=0.f, s1=0.f, s2=0.f, s3=0.f;
    #pragma unroll 4
    for (int k = 0; k < DIM; k += 4) {
        s0 += bh[k+0]*swq[(k+0)*DIM + nn];
        s1 += bh[k+1]*swq[(k+1)*DIM + nn];
        s2 += bh[k+2]*swq[(k+2)*DIM + nn];
        s3 += bh[k+3]*swq[(k+3)*DIM + nn];
    }
    g_bq2[n] = sbq[nn] + ((s0+s1)+(s2+s3));
}

// ---------------- conv1d over prev_attn -------------------------------------
__global__ void conv_k(const float* __restrict__ prev,
                       const float* __restrict__ w,
                       const float* __restrict__ cb)
{
    int idx = blockIdx.x*blockDim.x + threadIdx.x;
    if (idx >= NB*CHN*VLEN) return;
    int vl = idx % VLEN;
    int c  = (idx / VLEN) % CHN;
    int bn = idx / (VLEN*CHN);
    const float* p = prev + (size_t)bn*VLEN;
    float w0 = w[c*3+0], w1 = w[c*3+1], w2 = w[c*3+2];
    float s = cb[c] + p[vl]*w1;
    if (vl > 0)       s += p[vl-1]*w0;
    if (vl < VLEN-1)  s += p[vl+1]*w2;
    g_conv[idx] = s;
}

// ---------------- TF32 tensor-core GEMM --------------------------------------
// CTA tile 64x128x16, 3-stage SMEM ring, ONE __syncthreads per stage.
// 4 warps (2x2), warp 32x64. __launch_bounds__(128,3) -> 3 CTAs/SM.
// MODE 1: g_v = cvt(value)@g_wv + bias + loc(conv,Wloc) (round; Cext=Wloc)
// MODE 2: z<64: g_kk = head(g_v)@g_swk + sbk; z>=64: g_vv = head(g_v)@g_swv + sbv
// MODE 3: attn = g_qq @ g_kk^T * (1/16)  (exact; VAR1 C=g_attn)  64x 512x512x256
// MODE 4: g_ctx = cvt(attn) @ g_vv       (round; VAR1 A=g_attn)  64x 512x256x512
// MODE 5: out = tanh(cvt([g_ctx|query]) @ g_wout + bout)    M=8192 N=1024 K=2048
// MODE 6: g_wq2 col-block h = cvt(Wq[:,h]) @ g_swq (round)  4x  1024x256x256
// MODE 7: g_qq = cvt(query) @ g_wq2 + g_bq2 (head scatter, round) M=8192 N=1024 K=1024
template<int MODE, int VAR>
__global__ __launch_bounds__(128, 3) void mma_k(
    const float* __restrict__ P0, const float* __restrict__ bias,
    float* __restrict__ Cext)
{
    constexpr bool TB   = (MODE==3);
    constexpr bool CVTA = (MODE==1 || MODE==4 || MODE==5 || MODE==6 || MODE==7);
    constexpr int K    = (MODE==1)?1024 : (MODE==2)?256 : (MODE==3)?256 :
                         (MODE==4)?512  : (MODE==5)?2048 : (MODE==6)?256 : 1024;
    constexpr int LDA  = (MODE==1)?1024 : (MODE==2)?1024 : (MODE==3)?256 :
                         (MODE==4)?512  : (MODE==5)?1024 : (MODE==6)?1024 : 1024;
    constexpr int LDB  = (MODE==1)?1024 : (MODE==2)?256 : (MODE==3)?256 :
                         (MODE==4)?256  : (MODE==5)?1024 : (MODE==6)?256 : 1024;
    constexpr int LDC  = (MODE==1)?1024 : (MODE==2)?256 : (MODE==3)?512 :
                         (MODE==4)?1024 : (MODE==5)?1024 : (MODE==6)?1024 : 1024;
    constexpr int A_STAGE = 64*20;
    constexpr int B_STAGE = TB ? 128*20 : 16*136;
    constexpr int NS   = K/16;

    __shared__ float SA[3*A_STAGE];
    __shared__ float SB[3*B_STAGE];

    const int m0 = blockIdx.y*64, n0 = blockIdx.x*128;
    const int zz = blockIdx.z;

    const float* Ab; const float* Bb; float* Cb;
    const float* bias2 = bias;
    if (MODE==1) {
        Ab = P0; Bb = g_wv; Cb = g_v;
    } else if (MODE==2) {
        int half = zz >> 6, z = zz & 63;
        int b = z & 15, h = z >> 4;
        Ab = g_v + (size_t)b*QLEN*HID + (size_t)h*DIM;
        Bb = half ? g_swv : g_swk;
        Cb = (half ? g_vv : g_kk) + (size_t)z*QLEN*DIM;
        bias2 = half ? P0 : bias;     // P0 carries sbv, bias carries sbk
    } else if (MODE==3) {
        Ab = g_qq + (size_t)zz*QLEN*DIM;
        Bb = g_kk + (size_t)zz*VLEN*DIM;
        Cb = ((VAR==1) ? g_attn : Cext) + (size_t)zz*QLEN*VLEN;
    } else if (MODE==4) {
        int b = zz & 15, h = zz >> 4;
        Ab = ((VAR==1) ? g_attn : P0) + (size_t)zz*QLEN*VLEN;
        Bb = g_vv + (size_t)zz*VLEN*DIM;
        Cb = g_ctx + (size_t)b*QLEN*HID + (size_t)h*DIM;
    } else if (MODE==5) {
        Ab = g_ctx; Bb = g_wout; Cb = Cext;
    } else if (MODE==6) {
        Ab = P0 + (size_t)zz*DIM;     // Wq col block h
        Bb = g_swq;
        Cb = g_wq2 + (size_t)zz*DIM;
    } else { // MODE 7
        Ab = P0; Bb = g_wq2; Cb = g_qq;  // Cb unused (scatter epilogue)
    }

    const int tid  = threadIdx.x;
    const int lane = tid & 31, wid = tid >> 5;
    const int wm   = wid >> 1, wn = wid & 1;        // 2x2 warp grid
    const int gid  = lane >> 2, tig = lane & 3;

    float acc[2][8][4] = {};                         // 32x64 warp tile

    auto load_stage = [&](int s, int buf) {
        int k0 = s*16;
        const float* Ap = Ab; int kc = k0;
        if (MODE==5 && k0 >= 1024) { Ap = P0; kc = k0 - 1024; }   // concat: query half
        float* sa = SA + buf*A_STAGE;
        #pragma unroll
        for (int i = 0; i < 2; i++) {
            int r = i*32 + (tid>>2), c = (tid&3)*4;
            cp16(sa + r*20 + c, Ap + (size_t)(m0+r)*LDA + kc + c);
        }
        float* sb = SB + buf*B_STAGE;
        if (!TB) {
            #pragma unroll
            for (int i = 0; i < 4; i++) {
                int r = i*4 + (tid>>5), c = (tid&31)*4;
                cp16(sb + r*136 + c, Bb + (size_t)(k0+r)*LDB + n0 + c);
            }
        } else {
            #pragma unroll
            for (int i = 0; i < 4; i++) {
                int r = i*32 + (tid>>2), c = (tid&3)*4;
                cp16(sb + r*20 + c, Bb + (size_t)(n0+r)*LDB + k0 + c);
            }
        }
        asm volatile("cp.async.commit_group;");
    };

    auto compute_stage = [&](const float* sa, const float* sb) {
        #pragma unroll
        for (int kk = 0; kk < 2; kk++) {
            const int kc = kk*8;
            uint32_t af[2][4];
            #pragma unroll
            for (int mt = 0; mt < 2; mt++) {
                int r = wm*32 + mt*16 + gid;
                if (CVTA) {
                    af[mt][0] = f2tf(sa[(r  )*20 + kc + tig    ]);
                    af[mt][1] = f2tf(sa[(r+8)*20 + kc + tig    ]);
                    af[mt][2] = f2tf(sa[(r  )*20 + kc + tig + 4]);
                    af[mt][3] = f2tf(sa[(r+8)*20 + kc + tig + 4]);
                } else {
                    af[mt][0] = __float_as_uint(sa[(r  )*20 + kc + tig    ]);
                    af[mt][1] = __float_as_uint(sa[(r+8)*20 + kc + tig    ]);
                    af[mt][2] = __float_as_uint(sa[(r  )*20 + kc + tig + 4]);
                    af[mt][3] = __float_as_uint(sa[(r+8)*20 + kc + tig + 4]);
                }
            }
            uint32_t bf[8][2];
            #pragma unroll
            for (int nt = 0; nt < 8; nt++) {
                int cb = wn*64 + nt*8 + gid;
                if (!TB) {
                    bf[nt][0] = __float_as_uint(sb[(kc+tig  )*136 + cb]);
                    bf[nt][1] = __float_as_uint(sb[(kc+tig+4)*136 + cb]);
                } else {
                    bf[nt][0] = __float_as_uint(sb[cb*20 + kc + tig    ]);
                    bf[nt][1] = __float_as_uint(sb[cb*20 + kc + tig + 4]);
                }
            }
            #pragma unroll
            for (int mt = 0; mt < 2; mt++)
                #pragma unroll
                for (int nt = 0; nt < 8; nt++)
                    mma8(acc[mt][nt], af[mt], bf[nt]);
        }
    };

    // ---- 3-stage ring, one barrier per stage -------------------------------
    load_stage(0, 0);
    if (NS > 1) load_stage(1, 1);
    int buf = 0;
    for (int s = 0; s < NS; s++) {
        if (s+1 < NS) asm volatile("cp.async.wait_group 1;");
        else          asm volatile("cp.async.wait_group 0;");
        __syncthreads();
        if (s+2 < NS) {
            int nb = buf+2; if (nb >= 3) nb -= 3;
            load_stage(s+2, nb);
        }
        compute_stage(SA + buf*A_STAGE, SB + buf*B_STAGE);
        if (++buf == 3) buf = 0;
    }
    __syncthreads();   // protect SA reuse below (MODE1) / uniform exit

    // ---- MODE1: stage conv/Wloc tiles for fused loc (reuse SA, now dead) ---
    float* CV = SA;            // [10][64]  conv slice (c, vl-m0)
    float* WL = SA + 640;      // [10][128] Wloc slice (c, d-base)
    if (MODE==1) {
        const int b = m0 >> 9, h = n0 >> 8, dbase = n0 & 255;
        const float* convb = g_conv + ((size_t)(b*NH+h)*CHN)*VLEN + (m0 & 511);
        const float* Wloc  = Cext;   // Cext carries Wloc for MODE1
        for (int i = tid; i < 640; i += 128) {
            int c = i >> 6, rr = i & 63;
            CV[i] = convb[(size_t)c*VLEN + rr];
        }
        for (int i = tid; i < 1280; i += 128) {
            int c = i >> 7, dd = i & 127;
            WL[i] = Wloc[c*DIM + dbase + dd];
        }
        __syncthreads();
    }

    // ---- epilogue ----------------------------------------------------------
    #pragma unroll
    for (int mt = 0; mt < 2; mt++) {
        #pragma unroll
        for (int nt = 0; nt < 8; nt++) {
            int row = m0 + wm*32 + mt*16 + gid;
            int col = n0 + wn*64 + nt*8 + 2*tig;
            float* c = acc[mt][nt];
            #pragma unroll
            for (int half = 0; half < 2; half++) {
                int r = row + half*8;
                float x0 = c[half*2+0], x1 = c[half*2+1];
                if (MODE==1) {
                    int rr = r - m0, cc = col - n0;
                    float l0 = 0.f, l1 = 0.f;
                    #pragma unroll
                    for (int ch = 0; ch < CHN; ch++) {
                        float cv = CV[ch*64 + rr];
                        l0 += cv*WL[ch*128 + cc];
                        l1 += cv*WL[ch*128 + cc + 1];
                    }
                    x0 = tf32r(x0 + bias2[col]   + l0);
                    x1 = tf32r(x1 + bias2[col+1] + l1);
                } else if (MODE==2) {
                    x0 = tf32r(x0 + bias2[col]);
                    x1 = tf32r(x1 + bias2[col+1]);
                } else if (MODE==3) {
                    x0 *= 0.0625f; x1 *= 0.0625f;   // 1/sqrt(256), exact f32
                } else if (MODE==4 || MODE==6) {
                    x0 = tf32r(x0); x1 = tf32r(x1);
                } else if (MODE==5) {
                    x0 = tanhf(x0 + bias2[col]);
                    x1 = tanhf(x1 + bias2[col+1]);
                } else if (MODE==7) {
                    x0 = tf32r(x0 + g_bq2[col]);
                    x1 = tf32r(x1 + g_bq2[col+1]);
                }
                float2 v; v.x = x0; v.y = x1;
                if (MODE==7) {
                    int h = col >> 8;
                    int z = h*16 + (r >> 9);
                    *(float2*)&g_qq[(size_t)z*QLEN*DIM + (size_t)(r & 511)*DIM + (col & 255)] = v;
                } else {
                    *(float2*)&Cb[(size_t)r*LDC + col] = v;
                }
            }
        }
    }
}

// ---------------- row softmax (warp per 512-wide row); GL=1 -> g_attn -------
template<int GL>
__global__ void softmax_k(float* __restrict__ attn_ext)
{
    int gw   = (blockIdx.x*blockDim.x + threadIdx.x) >> 5;
    int lane = threadIdx.x & 31;
    if (gw >= NB*QLEN) return;
    float* base = (GL==1) ? g_attn : attn_ext;
    float* row = base + (size_t)gw*VLEN;
    float4 v[4];
    float mx = -1e30f;
    #pragma unroll
    for (int r = 0; r < 4; r++) {
        v[r] = *(float4*)(row + (size_t)(lane + r*32)*4);
        mx = fmaxf(mx, fmaxf(fmaxf(v[r].x, v[r].y), fmaxf(v[r].z, v[r].w)));
    }
    #pragma unroll
    for (int o = 16; o; o >>= 1) mx = fmaxf(mx, __shfl_xor_sync(0xffffffffu, mx, o));
    float s = 0.f;
    #pragma unroll
    for (int r = 0; r < 4; r++) {
        v[r].x = expf(v[r].x - mx); v[r].y = expf(v[r].y - mx);
        v[r].z = expf(v[r].z - mx); v[r].w = expf(v[r].w - mx);
        s += v[r].x + v[r].y + v[r].z + v[r].w;
    }
    #pragma unroll
    for (int o = 16; o; o >>= 1) s += __shfl_xor_sync(0xffffffffu, s, o);
    float inv = 1.f / s;
    #pragma unroll
    for (int r = 0; r < 4; r++) {
        v[r].x *= inv; v[r].y *= inv; v[r].z *= inv; v[r].w *= inv;
        *(float4*)(row + (size_t)(lane + r*32)*4) = v[r];
    }
}

extern "C" void kernel_launch(void* const* d_in, const int* in_sizes, int n_in,
                              void* d_out, int out_size)
{
    const float* query  = (const float*)d_in[0];
    const float* value  = (const float*)d_in[1];
    const float* prev   = (const float*)d_in[2];
    const float* conv_w = (const float*)d_in[3];
    const float* conv_b = (const float*)d_in[4];
    const float* Wq     = (const float*)d_in[5];
    const float* bq     = (const float*)d_in[6];
    const float* Wv     = (const float*)d_in[7];
    const float* Wloc   = (const float*)d_in[8];
    const float* bias   = (const float*)d_in[9];
    const float* Wout   = (const float*)d_in[10];
    const float* bout   = (const float*)d_in[11];
    const float* swq    = (const float*)d_in[12];
    const float* sbq    = (const float*)d_in[13];
    const float* swk    = (const float*)d_in[14];
    const float* sbk    = (const float*)d_in[15];
    const float* swv    = (const float*)d_in[16];
    const float* sbv    = (const float*)d_in[17];

    float* out = (float*)d_out;

    const long long OUT_ELEMS  = (long long)Bsz*QLEN*HID;      // 8388608
    const long long ATTN_ELEMS = (long long)NB*QLEN*VLEN;      // 16777216
    const bool attn_in_out = ((long long)out_size >= OUT_ELEMS + ATTN_ELEMS);

    round_weights_k<<<(N4_TOT + 255)/256, 256>>>(Wv, Wout, swq, swk, swv);
    conv_k<<<(NB*CHN*VLEN + 255)/256, 256>>>(prev, conv_w, conv_b);
    b2_k  <<<16, 64>>>(bq, swq, sbq);

    // folded q path: Wq2 prep then direct qq GEMM
    mma_k<6,0><<<dim3(2,16,4),  128>>>(Wq,    nullptr, nullptr);
    mma_k<7,0><<<dim3(8,128,1), 128>>>(query, nullptr, nullptr);

    // v path (loc fused into epilogue; Cext carries Wloc)
    mma_k<1,0><<<dim3(8,128,1), 128>>>(value, bias, (float*)Wloc);
    // kk (z<64) + vv (z>=64) merged; bias=sbk, P0=sbv
    mma_k<2,0><<<dim3(2,8,128), 128>>>(sbv, sbk, nullptr);

    if (attn_in_out) {
        float* attn = out + OUT_ELEMS;
        mma_k<3,0><<<dim3(4,8,64), 128>>>(nullptr, nullptr, attn);
        softmax_k<0><<<(NB*QLEN*32 + 255)/256, 256>>>(attn);
        mma_k<4,0><<<dim3(2,8,64), 128>>>(attn, nullptr, nullptr);
    } else {
        mma_k<3,1><<<dim3(4,8,64), 128>>>(nullptr, nullptr, nullptr);
        softmax_k<1><<<(NB*QLEN*32 + 255)/256, 256>>>(nullptr);
        mma_k<4,1><<<dim3(2,8,64), 128>>>(nullptr, nullptr, nullptr);
    }

    mma_k<5,0><<<dim3(8,128,1), 128>>>(query, bout, out);
}